// round 15
// baseline (speedup 1.0000x reference)
#include <cuda_runtime.h>
#include <cuda_fp16.h>
#include <math_constants.h>
#include <cstdint>

#define T_TOK 32768
#define D_DIM 1408
#define P_DIM 256
#define KC0 64
#define KC1 128
#define KC2 256
#define KT  448
#define TAU 1e-4f

// ------------------- device scratch -------------------
static __device__ float  g_r[(size_t)T_TOK * P_DIM];      // approx zproj; fixA overwrites flagged rows with EXACT zproj
static __device__ float  g_S[(size_t)T_TOK * KT];         // approx scores (preserved for fixB windowing)
static __device__ float  g_ssq[KT];
static __device__ float  g_ssr[T_TOK];
static __device__ float  g_G01[KC0 * KC1];
static __device__ float  g_G02[KC0 * KC2];
static __device__ float  g_G12[KC1 * KC2];
static __device__ float  g_EW[(size_t)KT * D_DIM];
static __device__ int    g_idx[3 * T_TOK];
static __device__ float  g_losstok[T_TOK];
static __device__ int    g_flagged[T_TOK];
static __device__ int    g_flagcnt[1];
static __device__ int    g_flaglist[T_TOK];
static __device__ __half g_WhT[(size_t)P_DIM * D_DIM];    // W_in^T fp16 hi [256][1408]
static __device__ __half g_WlT[(size_t)P_DIM * D_DIM];    // W_in^T fp16 lo
static __device__ __half g_zh[(size_t)T_TOK * D_DIM];     // z fp16 hi
static __device__ __half g_zl[(size_t)T_TOK * D_DIM];     // z fp16 lo
static __device__ __half g_rhh[(size_t)T_TOK * P_DIM];    // zproj fp16 hi
static __device__ __half g_rhl[(size_t)T_TOK * P_DIM];    // zproj fp16 lo
static __device__ __half g_cbh[KT * P_DIM];               // codebooks fp16 hi
static __device__ __half g_cbl[KT * P_DIM];               // codebooks fp16 lo

// ------------------- helpers -------------------
__device__ __forceinline__ uint32_t smem_u32(const void* p) {
    uint32_t a;
    asm("{ .reg .u64 t; cvta.to.shared.u64 t, %1; cvt.u32.u64 %0, t; }" : "=r"(a) : "l"(p));
    return a;
}
__device__ __forceinline__ void ldm4(uint32_t r[4], uint32_t a) {
    asm volatile("ldmatrix.sync.aligned.m8n8.x4.shared.b16 {%0,%1,%2,%3}, [%4];"
                 : "=r"(r[0]), "=r"(r[1]), "=r"(r[2]), "=r"(r[3]) : "r"(a));
}
__device__ __forceinline__ void mma_fp16(float c[4], const uint32_t a[4], const uint32_t b[2]) {
    asm volatile("mma.sync.aligned.m16n8k16.row.col.f32.f16.f16.f32 "
                 "{%0,%1,%2,%3}, {%4,%5,%6,%7}, {%8,%9}, {%0,%1,%2,%3};"
                 : "+f"(c[0]), "+f"(c[1]), "+f"(c[2]), "+f"(c[3])
                 : "r"(a[0]), "r"(a[1]), "r"(a[2]), "r"(a[3]), "r"(b[0]), "r"(b[1]));
}
__device__ __forceinline__ void split_h(float v, __half& h, __half& l) {
    h = __float2half_rn(v);
    l = __float2half_rn(v - __half2float(h));
}
#define CP16(dst, src) asm volatile("cp.async.cg.shared.global [%0], [%1], 16;" :: "r"(dst), "l"(src))
#define CP_COMMIT() asm volatile("cp.async.commit_group;" ::: "memory")
#define CP_WAIT1() asm volatile("cp.async.wait_group 1;" ::: "memory")
#define CP_WAIT0() asm volatile("cp.async.wait_group 0;" ::: "memory")

// ------------------- zero counter -------------------
__global__ void k_zero1() { if (threadIdx.x == 0) g_flagcnt[0] = 0; }

// ------------------- z -> fp16 hi/lo -------------------
__global__ __launch_bounds__(256) void k_zprep(const float* __restrict__ z) {
    const size_t base = ((size_t)blockIdx.x * 256 + threadIdx.x) * 8;
    float4 v0 = *(const float4*)(z + base);
    float4 v1 = *(const float4*)(z + base + 4);
    float vv[8] = {v0.x, v0.y, v0.z, v0.w, v1.x, v1.y, v1.z, v1.w};
    __half h[8], l[8];
#pragma unroll
    for (int i = 0; i < 8; i++) split_h(vv[i], h[i], l[i]);
    __half2 ph[4], pl[4];
#pragma unroll
    for (int i = 0; i < 4; i++) {
        ph[i] = __halves2half2(h[2 * i], h[2 * i + 1]);
        pl[i] = __halves2half2(l[2 * i], l[2 * i + 1]);
    }
    *(uint4*)(g_zh + base) = make_uint4(*(uint32_t*)&ph[0], *(uint32_t*)&ph[1],
                                        *(uint32_t*)&ph[2], *(uint32_t*)&ph[3]);
    *(uint4*)(g_zl + base) = make_uint4(*(uint32_t*)&pl[0], *(uint32_t*)&pl[1],
                                        *(uint32_t*)&pl[2], *(uint32_t*)&pl[3]);
}

// ------------------- W_in -> fp16 hi/lo transpose -------------------
__global__ __launch_bounds__(256) void k_wprep(const float* __restrict__ Win) {
    __shared__ float tile[32][33];
    const int r0 = blockIdx.x * 32, c0 = blockIdx.y * 32;
    const int tx = threadIdx.x & 31, ty = threadIdx.x >> 5;
    for (int rr = ty; rr < 32; rr += 8)
        tile[rr][tx] = Win[(size_t)(r0 + rr) * P_DIM + c0 + tx];
    __syncthreads();
    for (int rr = ty; rr < 32; rr += 8) {
        __half h, l;
        split_h(tile[tx][rr], h, l);
        g_WhT[(size_t)(c0 + rr) * D_DIM + r0 + tx] = h;
        g_WlT[(size_t)(c0 + rr) * D_DIM + r0 + tx] = l;
    }
}

// ------------------- codebooks -> fp16 hi/lo -------------------
__global__ __launch_bounds__(256) void k_cbprep(const float* __restrict__ e0,
                                                const float* __restrict__ e1,
                                                const float* __restrict__ e2) {
    const int row = blockIdx.x;
    const float* src = (row < KC0) ? (e0 + (size_t)row * P_DIM)
                     : (row < KC0 + KC1) ? (e1 + (size_t)(row - KC0) * P_DIM)
                                         : (e2 + (size_t)(row - KC0 - KC1) * P_DIM);
    __half h, l;
    split_h(src[threadIdx.x], h, l);
    g_cbh[row * P_DIM + threadIdx.x] = h;
    g_cbl[row * P_DIM + threadIdx.x] = l;
}

// ------------------- ssq (exact fp32 sequential order) -------------------
__global__ __launch_bounds__(256) void k_ssqE(const float* __restrict__ e0,
                                              const float* __restrict__ e1,
                                              const float* __restrict__ e2) {
    __shared__ float buf[8][260];
    const int warp = threadIdx.x >> 5, lane = threadIdx.x & 31;
    const int r = blockIdx.x * 8 + warp;
    if (r >= KT) return;
    const float* src = (r < KC0) ? (e0 + (size_t)r * P_DIM)
                     : (r < KC0 + KC1) ? (e1 + (size_t)(r - KC0) * P_DIM)
                                       : (e2 + (size_t)(r - KC0 - KC1) * P_DIM);
#pragma unroll
    for (int k = 0; k < 8; k++) buf[warp][lane + 32 * k] = src[lane + 32 * k];
    __syncwarp();
    if (lane == 0) {
        float s = 0.f;
        for (int p = 0; p < P_DIM; p++) s = __fadd_rn(s, __fmul_rn(buf[warp][p], buf[warp][p]));
        g_ssq[r] = s;
    }
}

// ------------------- Gram tables -------------------
__global__ __launch_bounds__(256) void k_tables(const float* __restrict__ e0,
                                                const float* __restrict__ e1,
                                                const float* __restrict__ e2) {
    int gw = (blockIdx.x * 256 + threadIdx.x) >> 5;
    int lane = threadIdx.x & 31;
    if (gw >= 57344) return;
    const float *a, *b;
    float* dst;
    if (gw < 8192) {
        a = e0 + (size_t)(gw >> 7) * P_DIM;
        b = e1 + (size_t)(gw & 127) * P_DIM;
        dst = g_G01 + gw;
    } else if (gw < 24576) {
        int id = gw - 8192;
        a = e0 + (size_t)(id >> 8) * P_DIM;
        b = e2 + (size_t)(id & 255) * P_DIM;
        dst = g_G02 + id;
    } else {
        int id = gw - 24576;
        a = e1 + (size_t)(id >> 8) * P_DIM;
        b = e2 + (size_t)(id & 255) * P_DIM;
        dst = g_G12 + id;
    }
    float s = 0.f;
#pragma unroll
    for (int k = 0; k < 8; k++) s += a[lane + 32 * k] * b[lane + 32 * k];
#pragma unroll
    for (int o = 16; o; o >>= 1) s += __shfl_xor_sync(0xffffffffu, s, o);
    if (lane == 0) *dst = s;
}

// ------------------- GEMM1: fp16 hi/lo x3, cp.async double-buffer ---------------------
// Dynamic smem: 2 buffers x 61440B. Layout per buffer (bytes):
//   Ah 0..10239, Al 10240..20479, Bh 20480..40959, Bl 40960..61439
__global__ __launch_bounds__(512) void k_gemm1_mma(const float* __restrict__ bin) {
    extern __shared__ __half smp[];
    const uint32_t sbase = smem_u32(smp);
    const int tid = threadIdx.x, wid = tid >> 5, lane = tid & 31;
    const int warp_m = wid >> 3, warp_n = wid & 7;
    const size_t bm = (size_t)blockIdx.x * 128;
    const int g = lane >> 3, lr = lane & 7;
    const int a_r = tid >> 2, a_c = tid & 3;
    const int b_r0 = (tid * 2) >> 2, b_c0 = (tid * 2) & 3;
    const int b_r1 = (tid * 2 + 1) >> 2, b_c1 = (tid * 2 + 1) & 3;

    float acc[4][4][4];
#pragma unroll
    for (int mt = 0; mt < 4; mt++)
#pragma unroll
        for (int nt = 0; nt < 4; nt++)
#pragma unroll
            for (int q = 0; q < 4; q++) acc[mt][nt][q] = 0.f;

    auto issue = [&](int kc) {
        const uint32_t sb = sbase + (kc & 1) * 61440;
        const int k0 = kc * 32;
        CP16(sb + (uint32_t)(a_r * 80 + a_c * 16),
             g_zh + (bm + a_r) * D_DIM + k0 + a_c * 8);
        CP16(sb + 10240u + (uint32_t)(a_r * 80 + a_c * 16),
             g_zl + (bm + a_r) * D_DIM + k0 + a_c * 8);
        CP16(sb + 20480u + (uint32_t)(b_r0 * 80 + b_c0 * 16),
             g_WhT + (size_t)b_r0 * D_DIM + k0 + b_c0 * 8);
        CP16(sb + 20480u + (uint32_t)(b_r1 * 80 + b_c1 * 16),
             g_WhT + (size_t)b_r1 * D_DIM + k0 + b_c1 * 8);
        CP16(sb + 40960u + (uint32_t)(b_r0 * 80 + b_c0 * 16),
             g_WlT + (size_t)b_r0 * D_DIM + k0 + b_c0 * 8);
        CP16(sb + 40960u + (uint32_t)(b_r1 * 80 + b_c1 * 16),
             g_WlT + (size_t)b_r1 * D_DIM + k0 + b_c1 * 8);
        CP_COMMIT();
    };

    issue(0);
    const int NK = D_DIM / 32;
    for (int kc = 0; kc < NK; kc++) {
        if (kc + 1 < NK) { issue(kc + 1); CP_WAIT1(); }
        else             { CP_WAIT0(); }
        __syncthreads();
        const uint32_t sb = sbase + (kc & 1) * 61440;
#pragma unroll
        for (int ks = 0; ks < 2; ks++) {
            const int kk = ks * 16;
            uint32_t bhf[4][2], blf[4][2];
#pragma unroll
            for (int p = 0; p < 2; p++) {
                const int n0 = warp_n * 32 + p * 16;
                uint32_t off = (uint32_t)((n0 + ((g >> 1) << 3) + lr) * 40 + kk + ((g & 1) << 3)) * 2;
                uint32_t t[4];
                ldm4(t, sb + 20480u + off);
                bhf[p * 2][0] = t[0]; bhf[p * 2][1] = t[1];
                bhf[p * 2 + 1][0] = t[2]; bhf[p * 2 + 1][1] = t[3];
                ldm4(t, sb + 40960u + off);
                blf[p * 2][0] = t[0]; blf[p * 2][1] = t[1];
                blf[p * 2 + 1][0] = t[2]; blf[p * 2 + 1][1] = t[3];
            }
#pragma unroll
            for (int mt = 0; mt < 4; mt++) {
                const int m0 = warp_m * 64 + mt * 16;
                uint32_t aoff = (uint32_t)((m0 + ((g & 1) << 3) + lr) * 40 + kk + ((g >> 1) << 3)) * 2;
                uint32_t ah[4], al[4];
                ldm4(ah, sb + aoff);
                ldm4(al, sb + 10240u + aoff);
#pragma unroll
                for (int nt = 0; nt < 4; nt++) {
                    mma_fp16(acc[mt][nt], ah, bhf[nt]);
                    mma_fp16(acc[mt][nt], ah, blf[nt]);
                    mma_fp16(acc[mt][nt], al, bhf[nt]);
                }
            }
        }
        __syncthreads();
    }
#pragma unroll
    for (int mt = 0; mt < 4; mt++) {
        const size_t row = bm + warp_m * 64 + mt * 16 + (lane >> 2);
#pragma unroll
        for (int nt = 0; nt < 4; nt++) {
            const int col = warp_n * 32 + nt * 8 + ((lane & 3) << 1);
            float b0 = bin[col], b1 = bin[col + 1];
            float v0 = acc[mt][nt][0] + b0, v1 = acc[mt][nt][1] + b1;
            float v2 = acc[mt][nt][2] + b0, v3 = acc[mt][nt][3] + b1;
            *(float2*)(g_r + row * P_DIM + col) = make_float2(v0, v1);
            *(float2*)(g_r + (row + 8) * P_DIM + col) = make_float2(v2, v3);
            __half h0, l0, h1, l1;
            split_h(v0, h0, l0); split_h(v1, h1, l1);
            __half2 ph = __halves2half2(h0, h1), pl = __halves2half2(l0, l1);
            *(uint32_t*)(g_rhh + row * P_DIM + col) = *(uint32_t*)&ph;
            *(uint32_t*)(g_rhl + row * P_DIM + col) = *(uint32_t*)&pl;
            split_h(v2, h0, l0); split_h(v3, h1, l1);
            ph = __halves2half2(h0, h1); pl = __halves2half2(l0, l1);
            *(uint32_t*)(g_rhh + (row + 8) * P_DIM + col) = *(uint32_t*)&ph;
            *(uint32_t*)(g_rhl + (row + 8) * P_DIM + col) = *(uint32_t*)&pl;
        }
    }
}

// ------------------- GEMMS: fp16 hi/lo x3, reg-staged -------------------
__global__ __launch_bounds__(256) void k_gemmS_mma() {
    __shared__ __half Ah[128][40], Al[128][40], Bh[64][40], Bl[64][40];
    const int tid = threadIdx.x, wid = tid >> 5, lane = tid & 31;
    const int warp_m = wid >> 1, warp_n = wid & 1;
    const size_t bm = (size_t)blockIdx.y * 128;
    const int bn = blockIdx.x * 64;
    const uint32_t sAh = smem_u32(Ah), sAl = smem_u32(Al);
    const uint32_t sBh = smem_u32(Bh), sBl = smem_u32(Bl);
    const int g = lane >> 3, lr = lane & 7;
    const int a_r0 = (tid * 2) >> 2, a_c0 = (tid * 2) & 3;
    const int a_r1 = (tid * 2 + 1) >> 2, a_c1 = (tid * 2 + 1) & 3;
    const int b_r = tid >> 2, b_c = tid & 3;

    float acc[2][4][4];
#pragma unroll
    for (int mt = 0; mt < 2; mt++)
#pragma unroll
        for (int nt = 0; nt < 4; nt++)
#pragma unroll
            for (int q = 0; q < 4; q++) acc[mt][nt][q] = 0.f;

    uint4 rAh[2], rAl[2], rBh, rBl;
    auto load_tile = [&](int kc) {
        const int k0 = kc * 32;
        rAh[0] = *(const uint4*)(g_rhh + (bm + a_r0) * P_DIM + k0 + a_c0 * 8);
        rAh[1] = *(const uint4*)(g_rhh + (bm + a_r1) * P_DIM + k0 + a_c1 * 8);
        rAl[0] = *(const uint4*)(g_rhl + (bm + a_r0) * P_DIM + k0 + a_c0 * 8);
        rAl[1] = *(const uint4*)(g_rhl + (bm + a_r1) * P_DIM + k0 + a_c1 * 8);
        rBh = *(const uint4*)(g_cbh + (size_t)(bn + b_r) * P_DIM + k0 + b_c * 8);
        rBl = *(const uint4*)(g_cbl + (size_t)(bn + b_r) * P_DIM + k0 + b_c * 8);
    };
    auto store_tile = [&]() {
        *(uint4*)&Ah[a_r0][a_c0 * 8] = rAh[0];
        *(uint4*)&Ah[a_r1][a_c1 * 8] = rAh[1];
        *(uint4*)&Al[a_r0][a_c0 * 8] = rAl[0];
        *(uint4*)&Al[a_r1][a_c1 * 8] = rAl[1];
        *(uint4*)&Bh[b_r][b_c * 8] = rBh;
        *(uint4*)&Bl[b_r][b_c * 8] = rBl;
    };

    load_tile(0);
    for (int kc = 0; kc < P_DIM / 32; kc++) {
        store_tile();
        __syncthreads();
        if (kc + 1 < P_DIM / 32) load_tile(kc + 1);
#pragma unroll
        for (int ks = 0; ks < 2; ks++) {
            const int kk = ks * 16;
            uint32_t bhf[4][2], blf[4][2];
#pragma unroll
            for (int p = 0; p < 2; p++) {
                const int n0 = warp_n * 32 + p * 16;
                uint32_t off = (uint32_t)((n0 + ((g >> 1) << 3) + lr) * 40 + kk + ((g & 1) << 3)) * 2;
                uint32_t t[4];
                ldm4(t, sBh + off);
                bhf[p * 2][0] = t[0]; bhf[p * 2][1] = t[1];
                bhf[p * 2 + 1][0] = t[2]; bhf[p * 2 + 1][1] = t[3];
                ldm4(t, sBl + off);
                blf[p * 2][0] = t[0]; blf[p * 2][1] = t[1];
                blf[p * 2 + 1][0] = t[2]; blf[p * 2 + 1][1] = t[3];
            }
#pragma unroll
            for (int mt = 0; mt < 2; mt++) {
                const int m0 = warp_m * 32 + mt * 16;
                uint32_t aoff = (uint32_t)((m0 + ((g & 1) << 3) + lr) * 40 + kk + ((g >> 1) << 3)) * 2;
                uint32_t ah[4], al[4];
                ldm4(ah, sAh + aoff);
                ldm4(al, sAl + aoff);
#pragma unroll
                for (int nt = 0; nt < 4; nt++) {
                    mma_fp16(acc[mt][nt], ah, bhf[nt]);
                    mma_fp16(acc[mt][nt], ah, blf[nt]);
                    mma_fp16(acc[mt][nt], al, bhf[nt]);
                }
            }
        }
        __syncthreads();
    }
#pragma unroll
    for (int mt = 0; mt < 2; mt++) {
        const size_t row = bm + warp_m * 32 + mt * 16 + (lane >> 2);
#pragma unroll
        for (int nt = 0; nt < 4; nt++) {
            const int col = bn + warp_n * 32 + nt * 8 + ((lane & 3) << 1);
            *(float2*)(g_S + row * KT + col) = make_float2(acc[mt][nt][0], acc[mt][nt][1]);
            *(float2*)(g_S + (row + 8) * KT + col) = make_float2(acc[mt][nt][2], acc[mt][nt][3]);
        }
    }
}

// ------------------- ssr -------------------
__global__ __launch_bounds__(256) void k_ssr() {
    const int warp = threadIdx.x >> 5, lane = threadIdx.x & 31;
    const size_t t = (size_t)blockIdx.x * 8 + warp;
    const float* rr = g_r + t * P_DIM;
    float s = 0.f;
#pragma unroll
    for (int k = 0; k < 8; k++) { float v = rr[lane + 32 * k]; s += v * v; }
#pragma unroll
    for (int o = 16; o; o >>= 1) s += __shfl_xor_sync(0xffffffffu, s, o);
    if (lane == 0) g_ssr[t] = s;
}

// ------------------- cascade pick -------------------
__device__ __forceinline__ void top2_reduce(float& m1, float& m2, int& i1) {
#pragma unroll
    for (int o = 16; o; o >>= 1) {
        float om1 = __shfl_xor_sync(0xffffffffu, m1, o);
        int   oi1 = __shfl_xor_sync(0xffffffffu, i1, o);
        float om2 = __shfl_xor_sync(0xffffffffu, m2, o);
        if (om1 < m1 || (om1 == m1 && oi1 < i1)) { m2 = fminf(m1, om2); m1 = om1; i1 = oi1; }
        else m2 = fminf(m2, om1);
    }
}

__global__ __launch_bounds__(256) void k_pickcas(float* __restrict__ out_idxf) {
    __shared__ float ssq_s[KT];
    for (int i = threadIdx.x; i < KT; i += 256) ssq_s[i] = g_ssq[i];
    __syncthreads();
    const int warp = threadIdx.x >> 5, lane = threadIdx.x & 31;
    const int t = blockIdx.x * 8 + warp;
    const float* Srow = g_S + (size_t)t * KT;

    float m1 = CUDART_INF_F, m2 = CUDART_INF_F; int i1 = 0x7fffffff;
#pragma unroll
    for (int kc = 0; kc < 2; kc++) {
        int j = kc * 32 + lane;
        float d = ssq_s[j] - 2.0f * Srow[j];
        if (d < m1) { m2 = m1; m1 = d; i1 = j; } else m2 = fminf(m2, d);
    }
    top2_reduce(m1, m2, i1);
    const int i0 = i1; const float mv0 = m1, gap0 = m2 - m1;

    const float* g01 = g_G01 + i0 * KC1;
    m1 = CUDART_INF_F; m2 = CUDART_INF_F; i1 = 0x7fffffff;
#pragma unroll
    for (int kc = 0; kc < 4; kc++) {
        int j = kc * 32 + lane;
        float d = ssq_s[KC0 + j] - 2.0f * (Srow[KC0 + j] - g01[j]);
        if (d < m1) { m2 = m1; m1 = d; i1 = j; } else m2 = fminf(m2, d);
    }
    top2_reduce(m1, m2, i1);
    const int idx1 = i1; const float mv1 = m1, gap1 = m2 - m1;

    const float* g02 = g_G02 + i0 * KC2;
    const float* g12 = g_G12 + idx1 * KC2;
    m1 = CUDART_INF_F; m2 = CUDART_INF_F; i1 = 0x7fffffff;
#pragma unroll
    for (int kc = 0; kc < 8; kc++) {
        int j = kc * 32 + lane;
        float d = ssq_s[KC0 + KC1 + j] - 2.0f * (Srow[KC0 + KC1 + j] - g02[j] - g12[j]);
        if (d < m1) { m2 = m1; m1 = d; i1 = j; } else m2 = fminf(m2, d);
    }
    top2_reduce(m1, m2, i1);
    const int idx2 = i1; const float mv2 = m1, gap2 = m2 - m1;

    if (lane == 0) {
        g_idx[t] = i0; g_idx[T_TOK + t] = idx1; g_idx[2 * T_TOK + t] = idx2;
        out_idxf[t] = (float)i0;
        out_idxf[T_TOK + t] = (float)idx1;
        out_idxf[2 * T_TOK + t] = (float)idx2;
        g_flagged[t] = (gap0 < TAU || gap1 < TAU || gap2 < TAU) ? 1 : 0;
        float s = g_ssr[t];
        g_losstok[t] = 3.f * s + 3.f * mv0 + 2.f * mv1 + mv2;
    }
}

// ------------------- compact -------------------
__global__ __launch_bounds__(256) void k_compact() {
    int i = blockIdx.x * 256 + threadIdx.x;
    for (; i < T_TOK; i += gridDim.x * 256)
        if (g_flagged[i]) g_flaglist[atomicAdd(&g_flagcnt[0], 1)] = i;
}

// ------------------- fixup A: exact zproj for flagged tokens -> g_r ------------------
__global__ __launch_bounds__(256) void k_fixA(const float* __restrict__ z,
                                              const float* __restrict__ Win,
                                              const float* __restrict__ bin) {
    extern __shared__ char sm[];
    float* zsm = (float*)sm;
    float* Wsm = (float*)(sm + 32 * 68 * 4);
    __shared__ int tl[32];
    const int tid = threadIdx.x;
    const int cnt = g_flagcnt[0];
    if (cnt == 0) return;

    for (int base = blockIdx.x * 32; base < cnt; base += gridDim.x * 32) {
        if (tid < 32) tl[tid] = g_flaglist[min(base + tid, cnt - 1)];
        __syncthreads();
        const int tg = tid >> 5, cg = tid & 31;
        float acc[4][8];
#pragma unroll
        for (int a = 0; a < 4; a++)
#pragma unroll
            for (int b = 0; b < 8; b++) acc[a][b] = 0.f;

        for (int kc = 0; kc < D_DIM / 64; kc++) {
#pragma unroll
            for (int q = 0; q < 2; q++) {
                int i = tid + q * 256;
                int s = i >> 4, c4 = i & 15;
                *(float4*)(zsm + s * 68 + c4 * 4) =
                    *(const float4*)(z + (size_t)tl[s] * D_DIM + kc * 64 + c4 * 4);
            }
#pragma unroll
            for (int q = 0; q < 16; q++) {
                int i = tid + q * 256;
                int k = i >> 6, c4 = i & 63;
                *(float4*)(Wsm + k * 256 + c4 * 4) =
                    *(const float4*)(Win + (size_t)(kc * 64 + k) * P_DIM + c4 * 4);
            }
            __syncthreads();
            for (int k = 0; k < 64; k++) {
                float4 w0 = *(const float4*)(Wsm + k * 256 + cg * 8);
                float4 w1 = *(const float4*)(Wsm + k * 256 + cg * 8 + 4);
                float wv[8] = {w0.x, w0.y, w0.z, w0.w, w1.x, w1.y, w1.z, w1.w};
#pragma unroll
                for (int a = 0; a < 4; a++) {
                    float zv = zsm[(tg * 4 + a) * 68 + k];
#pragma unroll
                    for (int b = 0; b < 8; b++)
                        acc[a][b] = __fmaf_rn(zv, wv[b], acc[a][b]);
                }
            }
            __syncthreads();
        }
#pragma unroll
        for (int a = 0; a < 4; a++) {
            int s = tg * 4 + a;
            if (base + s < cnt) {
                float* dst = g_r + (size_t)tl[s] * P_DIM;
#pragma unroll
                for (int b = 0; b < 8; b++)
                    dst[cg * 8 + b] = __fadd_rn(acc[a][b], bin[cg * 8 + b]);
            }
        }
        __syncthreads();
    }
}

// ------------------- fixup B: windowed exact replay -------------------
__global__ __launch_bounds__(256) void k_fixB(const float* __restrict__ e0,
                                              const float* __restrict__ e1,
                                              const float* __restrict__ e2,
                                              float* __restrict__ out_idxf) {
    __shared__ float r_sm[8][264];
    __shared__ int cand[8][64];
    __shared__ float ssq_sm[KT];
    const int tid = threadIdx.x, warp = tid >> 5, lane = tid & 31;
    const int cnt = g_flagcnt[0];
    if (cnt == 0) return;
    for (int i = tid; i < KT; i += 256) ssq_sm[i] = g_ssq[i];
    __syncthreads();

    const float* cbl_[3] = {e0, e1, e2};
    const int Kl[3] = {KC0, KC1, KC2};
    const int offl[3] = {0, KC0, KC0 + KC1};

    for (int base = blockIdx.x * 8 + warp; base < cnt; base += gridDim.x * 8) {
        const int t = g_flaglist[base];
#pragma unroll
        for (int k = 0; k < 8; k++)
            r_sm[warp][lane + 32 * k] = g_r[(size_t)t * P_DIM + lane + 32 * k];
        __syncwarp();
        float ssr;
        if (lane == 0) {
            float s = 0.f;
            for (int p = 0; p < P_DIM; p++)
                s = __fadd_rn(s, __fmul_rn(r_sm[warp][p], r_sm[warp][p]));
            ssr = s;
        }
        ssr = __shfl_sync(0xffffffffu, ssr, 0);

        const float* Srow = g_S + (size_t)t * KT;
        int idxs[3];
        double lsd = 0.0;
        int i0 = 0, i1e = 0;
        for (int lvl = 0; lvl < 3; lvl++) {
            const int K = Kl[lvl], off = offl[lvl];
            const float* cb = cbl_[lvl];
            const float* gr0 = (lvl == 1) ? (g_G01 + i0 * KC1)
                             : (lvl == 2) ? (g_G02 + i0 * KC2) : nullptr;
            const float* gr1 = (lvl == 2) ? (g_G12 + i1e * KC2) : nullptr;
            float dd[8];
            float m1 = CUDART_INF_F;
            for (int kc = 0; kc < K / 32; kc++) {
                int j = kc * 32 + lane;
                float s = Srow[off + j];
                if (gr0) s -= gr0[j];
                if (gr1) s -= gr1[j];
                float d = ssq_sm[off + j] - 2.0f * s;
                dd[kc] = d;
                m1 = fminf(m1, d);
            }
#pragma unroll
            for (int o = 16; o; o >>= 1) m1 = fminf(m1, __shfl_xor_sync(0xffffffffu, m1, o));
            const float thr = m1 + TAU;
            int n = 0;
            for (int kc = 0; kc < K / 32; kc++) {
                unsigned msk = __ballot_sync(0xffffffffu, dd[kc] <= thr);
                if ((dd[kc] <= thr)) {
                    int pos = n + __popc(msk & ((1u << lane) - 1));
                    if (pos < 64) cand[warp][pos] = kc * 32 + lane;
                }
                n += __popc(msk);
            }
            if (n > 64) n = 64;
            __syncwarp();
            float best = CUDART_INF_F; int bi = 0x7fffffff;
            for (int b0 = 0; b0 < n; b0 += 32) {
                int ci = b0 + lane;
                float dex = CUDART_INF_F; int jj = 0x7fffffff;
                if (ci < n) {
                    jj = cand[warp][ci];
                    const float* er = cb + (size_t)jj * P_DIM;
                    float a = 0.f;
                    for (int p = 0; p < P_DIM; p++)
                        a = __fmaf_rn(r_sm[warp][p], er[p], a);
                    dex = __fadd_rn(__fsub_rn(ssr, 2.0f * a), g_ssq[off + jj]);
                }
                float bm = dex; int bj = jj;
#pragma unroll
                for (int o = 16; o; o >>= 1) {
                    float od = __shfl_xor_sync(0xffffffffu, bm, o);
                    int   oi = __shfl_xor_sync(0xffffffffu, bj, o);
                    if (od < bm || (od == bm && oi < bj)) { bm = od; bj = oi; }
                }
                if (bm < best || (bm == best && bj < bi)) { best = bm; bi = bj; }
            }
            idxs[lvl] = bi;
            if (lvl == 0) i0 = bi; else if (lvl == 1) i1e = bi;
            const float* er = cb + (size_t)bi * P_DIM;
            double lp = 0.0;
#pragma unroll
            for (int k = 0; k < 8; k++) {
                int p = lane + 32 * k;
                float nv = __fsub_rn(r_sm[warp][p], er[p]);
                r_sm[warp][p] = nv;
                lp += (double)nv * (double)nv;
            }
            __syncwarp();
#pragma unroll
            for (int o = 16; o; o >>= 1) lp += __shfl_xor_sync(0xffffffffu, lp, o);
            lsd += lp;
            if (lvl < 2) {
                if (lane == 0) {
                    float s = 0.f;
                    for (int p = 0; p < P_DIM; p++)
                        s = __fadd_rn(s, __fmul_rn(r_sm[warp][p], r_sm[warp][p]));
                    ssr = s;
                }
                ssr = __shfl_sync(0xffffffffu, ssr, 0);
            }
        }
        if (lane == 0) {
            g_idx[t] = idxs[0]; g_idx[T_TOK + t] = idxs[1]; g_idx[2 * T_TOK + t] = idxs[2];
            out_idxf[t] = (float)idxs[0];
            out_idxf[T_TOK + t] = (float)idxs[1];
            out_idxf[2 * T_TOK + t] = (float)idxs[2];
            g_losstok[t] = (float)lsd;
        }
        __syncwarp();
    }
}

// ------------------- loss reduce -------------------
__global__ __launch_bounds__(256) void k_lossred(float* __restrict__ out_loss) {
    __shared__ double smm[256];
    double s = 0.0;
    for (int i = threadIdx.x; i < T_TOK; i += 256) s += (double)g_losstok[i];
    smm[threadIdx.x] = s;
    __syncthreads();
    for (int o = 128; o; o >>= 1) {
        if (threadIdx.x < o) smm[threadIdx.x] += smm[threadIdx.x + o];
        __syncthreads();
    }
    if (threadIdx.x == 0)
        *out_loss = (float)(smm[0] * (0.25 / (3.0 * (double)T_TOK * (double)P_DIM)));
}

// ------------------- EW = emb_cat @ W_out -------------------
__global__ __launch_bounds__(256) void k_ew(const float* __restrict__ e0,
                                            const float* __restrict__ e1,
                                            const float* __restrict__ e2,
                                            const float* __restrict__ Wout) {
    __shared__ float a[8][P_DIM];
    const int rbase = blockIdx.x * 8;
    for (int i = threadIdx.x; i < 8 * P_DIM; i += 256) {
        int r = rbase + i / P_DIM, p = i % P_DIM;
        const float* s = (r < KC0) ? (e0 + (size_t)r * P_DIM)
                       : (r < KC0 + KC1) ? (e1 + (size_t)(r - KC0) * P_DIM)
                                         : (e2 + (size_t)(r - KC0 - KC1) * P_DIM);
        a[i / P_DIM][p] = s[p];
    }
    __syncthreads();
    for (int c = threadIdx.x; c < D_DIM; c += 256) {
        float acc[8] = {0.f, 0.f, 0.f, 0.f, 0.f, 0.f, 0.f, 0.f};
        for (int p = 0; p < P_DIM; p++) {
            float w = Wout[(size_t)p * D_DIM + c];
#pragma unroll
            for (int r = 0; r < 8; r++) acc[r] = __fmaf_rn(a[r][p], w, acc[r]);
        }
#pragma unroll
        for (int r = 0; r < 8; r++) g_EW[(size_t)(rbase + r) * D_DIM + c] = acc[r];
    }
}

// ------------------- output gather -------------------
__global__ __launch_bounds__(352) void k_out(const float* __restrict__ bout,
                                             float* __restrict__ out) {
    const int t = blockIdx.x;
    const int i0 = g_idx[t], i1 = g_idx[T_TOK + t], i2 = g_idx[2 * T_TOK + t];
    const float4* r0 = (const float4*)(g_EW + (size_t)i0 * D_DIM);
    const float4* r1 = (const float4*)(g_EW + (size_t)(KC0 + i1) * D_DIM);
    const float4* r2 = (const float4*)(g_EW + (size_t)(KC0 + KC1 + i2) * D_DIM);
    const float4* bb = (const float4*)bout;
    float4* o = (float4*)(out + (size_t)t * D_DIM);
    const int c = threadIdx.x;
    float4 a = r0[c], b = r1[c], cc = r2[c], d = bb[c];
    o[c] = make_float4(a.x + b.x + cc.x + d.x, a.y + b.y + cc.y + d.y,
                       a.z + b.z + cc.z + d.z, a.w + b.w + cc.w + d.w);
}

// ------------------- launch -------------------
extern "C" void kernel_launch(void* const* d_in, const int* in_sizes, int n_in,
                              void* d_out, int out_size) {
    const float* z     = (const float*)d_in[0];
    const float* W_in  = (const float*)d_in[1];
    const float* b_in  = (const float*)d_in[2];
    const float* W_out = (const float*)d_in[3];
    const float* b_out = (const float*)d_in[4];
    const float* e0    = (const float*)d_in[5];
    const float* e1    = (const float*)d_in[6];
    const float* e2    = (const float*)d_in[7];

    float* out      = (float*)d_out;
    float* out_idxf = out + (size_t)T_TOK * D_DIM;
    float* out_loss = out_idxf + 3 * T_TOK;

    cudaFuncSetAttribute(k_gemm1_mma, cudaFuncAttributeMaxDynamicSharedMemorySize, 2 * 61440);
    cudaFuncSetAttribute(k_fixA, cudaFuncAttributeMaxDynamicSharedMemorySize,
                         32 * 68 * 4 + 64 * 256 * 4);

    k_zprep<<<(int)(((size_t)T_TOK * D_DIM) / (256 * 8)), 256>>>(z);
    k_wprep<<<dim3(D_DIM / 32, P_DIM / 32), 256>>>(W_in);
    k_zero1<<<1, 32>>>();
    k_gemm1_mma<<<T_TOK / 128, 512, 2 * 61440>>>(b_in);   // 4th launch -> profiled

    k_cbprep<<<KT, 256>>>(e0, e1, e2);
    k_ssqE<<<(KT + 7) / 8, 256>>>(e0, e1, e2);
    k_tables<<<7168, 256>>>(e0, e1, e2);
    k_ew<<<KT / 8, 256>>>(e0, e1, e2, W_out);

    k_ssr<<<T_TOK / 8, 256>>>();
    k_gemmS_mma<<<dim3(KT / 64, T_TOK / 128), 256>>>();
    k_pickcas<<<T_TOK / 8, 256>>>(out_idxf);

    k_compact<<<64, 256>>>();
    k_fixA<<<256, 256, 32 * 68 * 4 + 64 * 256 * 4>>>(z, W_in, b_in);
    k_fixB<<<512, 256>>>(e0, e1, e2, out_idxf);

    k_lossred<<<1, 256>>>(out_loss);
    k_out<<<T_TOK, 352>>>(b_out, out);
}

// round 16
// speedup vs baseline: 1.0680x; 1.0680x over previous
#include <cuda_runtime.h>
#include <cuda_fp16.h>
#include <math_constants.h>
#include <cstdint>

#define T_TOK 32768
#define D_DIM 1408
#define P_DIM 256
#define KC0 64
#define KC1 128
#define KC2 256
#define KT  448
#define TAU 1e-2f

// ------------------- device scratch -------------------
static __device__ float  g_r[(size_t)T_TOK * P_DIM];      // ONLY flagged rows valid (exact zproj from fixA)
static __device__ float  g_S[(size_t)T_TOK * KT];         // approx scores
static __device__ float  g_ssq[KT];
static __device__ float  g_G01[KC0 * KC1];
static __device__ float  g_G02[KC0 * KC2];
static __device__ float  g_G12[KC1 * KC2];
static __device__ float  g_EW[(size_t)KT * D_DIM];
static __device__ int    g_idx[3 * T_TOK];
static __device__ float  g_losstok[T_TOK];
static __device__ int    g_flagcnt[1];
static __device__ int    g_flaglist[T_TOK];
static __device__ __half g_WhT[(size_t)P_DIM * D_DIM];    // W_in^T fp16 [256][1408]
static __device__ __half g_rh[(size_t)T_TOK * P_DIM];     // zproj fp16
static __device__ __half g_cbh[KT * P_DIM];               // codebooks fp16

// ------------------- helpers -------------------
__device__ __forceinline__ uint32_t smem_u32(const void* p) {
    uint32_t a;
    asm("{ .reg .u64 t; cvta.to.shared.u64 t, %1; cvt.u32.u64 %0, t; }" : "=r"(a) : "l"(p));
    return a;
}
__device__ __forceinline__ void ldm4(uint32_t r[4], uint32_t a) {
    asm volatile("ldmatrix.sync.aligned.m8n8.x4.shared.b16 {%0,%1,%2,%3}, [%4];"
                 : "=r"(r[0]), "=r"(r[1]), "=r"(r[2]), "=r"(r[3]) : "r"(a));
}
__device__ __forceinline__ void mma_fp16(float c[4], const uint32_t a[4], const uint32_t b[2]) {
    asm volatile("mma.sync.aligned.m16n8k16.row.col.f32.f16.f16.f32 "
                 "{%0,%1,%2,%3}, {%4,%5,%6,%7}, {%8,%9}, {%0,%1,%2,%3};"
                 : "+f"(c[0]), "+f"(c[1]), "+f"(c[2]), "+f"(c[3])
                 : "r"(a[0]), "r"(a[1]), "r"(a[2]), "r"(a[3]), "r"(b[0]), "r"(b[1]));
}

// ------------------- zero counter -------------------
__global__ void k_zero1() { if (threadIdx.x == 0) g_flagcnt[0] = 0; }

// ------------------- W_in -> fp16 transpose -------------------
__global__ __launch_bounds__(256) void k_wprep(const float* __restrict__ Win) {
    __shared__ float tile[32][33];
    const int r0 = blockIdx.x * 32, c0 = blockIdx.y * 32;
    const int tx = threadIdx.x & 31, ty = threadIdx.x >> 5;
    for (int rr = ty; rr < 32; rr += 8)
        tile[rr][tx] = Win[(size_t)(r0 + rr) * P_DIM + c0 + tx];
    __syncthreads();
    for (int rr = ty; rr < 32; rr += 8)
        g_WhT[(size_t)(c0 + rr) * D_DIM + r0 + tx] = __float2half_rn(tile[tx][rr]);
}

// ------------------- codebooks -> fp16 + exact ssq -------------------
__global__ __launch_bounds__(256) void k_cbprep(const float* __restrict__ e0,
                                                const float* __restrict__ e1,
                                                const float* __restrict__ e2) {
    __shared__ float buf[P_DIM];
    const int row = blockIdx.x;
    const float* src = (row < KC0) ? (e0 + (size_t)row * P_DIM)
                     : (row < KC0 + KC1) ? (e1 + (size_t)(row - KC0) * P_DIM)
                                         : (e2 + (size_t)(row - KC0 - KC1) * P_DIM);
    float v = src[threadIdx.x];
    buf[threadIdx.x] = v;
    g_cbh[row * P_DIM + threadIdx.x] = __float2half_rn(v);
    __syncthreads();
    if (threadIdx.x == 0) {
        float s = 0.f;
        for (int p = 0; p < P_DIM; p++) s = __fadd_rn(s, __fmul_rn(buf[p], buf[p]));
        g_ssq[row] = s;
    }
}

// ------------------- Gram tables -------------------
__global__ __launch_bounds__(256) void k_tables(const float* __restrict__ e0,
                                                const float* __restrict__ e1,
                                                const float* __restrict__ e2) {
    int gw = (blockIdx.x * 256 + threadIdx.x) >> 5;
    int lane = threadIdx.x & 31;
    if (gw >= 57344) return;
    const float *a, *b;
    float* dst;
    if (gw < 8192) {
        a = e0 + (size_t)(gw >> 7) * P_DIM;
        b = e1 + (size_t)(gw & 127) * P_DIM;
        dst = g_G01 + gw;
    } else if (gw < 24576) {
        int id = gw - 8192;
        a = e0 + (size_t)(id >> 8) * P_DIM;
        b = e2 + (size_t)(id & 255) * P_DIM;
        dst = g_G02 + id;
    } else {
        int id = gw - 24576;
        a = e1 + (size_t)(id >> 8) * P_DIM;
        b = e2 + (size_t)(id & 255) * P_DIM;
        dst = g_G12 + id;
    }
    float s = 0.f;
#pragma unroll
    for (int k = 0; k < 8; k++) s += a[lane + 32 * k] * b[lane + 32 * k];
#pragma unroll
    for (int o = 16; o; o >>= 1) s += __shfl_xor_sync(0xffffffffu, s, o);
    if (lane == 0) *dst = s;
}

// ------------------- GEMM1: inline-cvt fp16, full N=256, 512 threads -----------------
__global__ __launch_bounds__(512) void k_gemm1_mma(const float* __restrict__ z,
                                                   const float* __restrict__ bin) {
    __shared__ __half Ah[128][40], Bh[256][40];
    const int tid = threadIdx.x, wid = tid >> 5, lane = tid & 31;
    const int warp_m = wid >> 3, warp_n = wid & 7;
    const size_t bm = (size_t)blockIdx.x * 128;
    const uint32_t sAh = smem_u32(Ah), sBh = smem_u32(Bh);
    const int g = lane >> 3, lr = lane & 7;
    // A: 1024 float4 items (row=i>>3, c4=i&7), 2/thread ; B: 1024 16B items (n=i>>2, c=i&3), 2/thread
    const int a_s0 = (tid * 2) >> 3, a_c0 = (tid * 2) & 7;
    const int a_s1 = (tid * 2 + 1) >> 3, a_c1 = (tid * 2 + 1) & 7;
    const int b_n0 = (tid * 2) >> 2, b_c0 = (tid * 2) & 3;
    const int b_n1 = (tid * 2 + 1) >> 2, b_c1 = (tid * 2 + 1) & 3;

    float acc[4][4][4];
#pragma unroll
    for (int mt = 0; mt < 4; mt++)
#pragma unroll
        for (int nt = 0; nt < 4; nt++)
#pragma unroll
            for (int q = 0; q < 4; q++) acc[mt][nt][q] = 0.f;

    float4 az[2];
    uint4 rB[2];
    auto load_tile = [&](int kc) {
        const int k0 = kc * 32;
        az[0] = *(const float4*)(z + (bm + a_s0) * D_DIM + k0 + a_c0 * 4);
        az[1] = *(const float4*)(z + (bm + a_s1) * D_DIM + k0 + a_c1 * 4);
        rB[0] = *(const uint4*)(g_WhT + (size_t)b_n0 * D_DIM + k0 + b_c0 * 8);
        rB[1] = *(const uint4*)(g_WhT + (size_t)b_n1 * D_DIM + k0 + b_c1 * 8);
    };
    auto store_tile = [&]() {
        __half2 p0 = __floats2half2_rn(az[0].x, az[0].y);
        __half2 p1 = __floats2half2_rn(az[0].z, az[0].w);
        *(uint2*)&Ah[a_s0][a_c0 * 4] = make_uint2(*(uint32_t*)&p0, *(uint32_t*)&p1);
        p0 = __floats2half2_rn(az[1].x, az[1].y);
        p1 = __floats2half2_rn(az[1].z, az[1].w);
        *(uint2*)&Ah[a_s1][a_c1 * 4] = make_uint2(*(uint32_t*)&p0, *(uint32_t*)&p1);
        *(uint4*)&Bh[b_n0][b_c0 * 8] = rB[0];
        *(uint4*)&Bh[b_n1][b_c1 * 8] = rB[1];
    };

    load_tile(0);
    const int NK = D_DIM / 32;
    for (int kc = 0; kc < NK; kc++) {
        store_tile();
        __syncthreads();
        if (kc + 1 < NK) load_tile(kc + 1);
#pragma unroll
        for (int ks = 0; ks < 2; ks++) {
            const int kk = ks * 16;
            uint32_t bf[4][2];
#pragma unroll
            for (int p = 0; p < 2; p++) {
                const int n0 = warp_n * 32 + p * 16;
                uint32_t off = (uint32_t)((n0 + ((g >> 1) << 3) + lr) * 40 + kk + ((g & 1) << 3)) * 2;
                uint32_t t[4];
                ldm4(t, sBh + off);
                bf[p * 2][0] = t[0]; bf[p * 2][1] = t[1];
                bf[p * 2 + 1][0] = t[2]; bf[p * 2 + 1][1] = t[3];
            }
#pragma unroll
            for (int mt = 0; mt < 4; mt++) {
                const int m0 = warp_m * 64 + mt * 16;
                uint32_t aoff = (uint32_t)((m0 + ((g & 1) << 3) + lr) * 40 + kk + ((g >> 1) << 3)) * 2;
                uint32_t ah[4];
                ldm4(ah, sAh + aoff);
#pragma unroll
                for (int nt = 0; nt < 4; nt++) mma_fp16(acc[mt][nt], ah, bf[nt]);
            }
        }
        __syncthreads();
    }
    // epilogue: + bias -> g_rh fp16 ONLY (fp32 zproj not materialized on fast path)
#pragma unroll
    for (int mt = 0; mt < 4; mt++) {
        const size_t row = bm + warp_m * 64 + mt * 16 + (lane >> 2);
#pragma unroll
        for (int nt = 0; nt < 4; nt++) {
            const int col = warp_n * 32 + nt * 8 + ((lane & 3) << 1);
            float b0 = bin[col], b1 = bin[col + 1];
            __half2 p = __floats2half2_rn(acc[mt][nt][0] + b0, acc[mt][nt][1] + b1);
            *(uint32_t*)(g_rh + row * P_DIM + col) = *(uint32_t*)&p;
            p = __floats2half2_rn(acc[mt][nt][2] + b0, acc[mt][nt][3] + b1);
            *(uint32_t*)(g_rh + (row + 8) * P_DIM + col) = *(uint32_t*)&p;
        }
    }
}

// ------------------- GEMMS: fp16 single-product (R14-proven) -------------------
__global__ __launch_bounds__(256) void k_gemmS_mma() {
    __shared__ __half Ah[128][40], Bh[64][40];
    const int tid = threadIdx.x, wid = tid >> 5, lane = tid & 31;
    const int warp_m = wid >> 1, warp_n = wid & 1;
    const size_t bm = (size_t)blockIdx.y * 128;
    const int bn = blockIdx.x * 64;
    const uint32_t sAh = smem_u32(Ah), sBh = smem_u32(Bh);
    const int g = lane >> 3, lr = lane & 7;
    const int a_r0 = (tid * 2) >> 2, a_c0 = (tid * 2) & 3;
    const int a_r1 = (tid * 2 + 1) >> 2, a_c1 = (tid * 2 + 1) & 3;
    const int b_r = tid >> 2, b_c = tid & 3;

    float acc[2][4][4];
#pragma unroll
    for (int mt = 0; mt < 2; mt++)
#pragma unroll
        for (int nt = 0; nt < 4; nt++)
#pragma unroll
            for (int q = 0; q < 4; q++) acc[mt][nt][q] = 0.f;

    uint4 rA[2], rB;
    auto load_tile = [&](int kc) {
        const int k0 = kc * 32;
        rA[0] = *(const uint4*)(g_rh + (bm + a_r0) * P_DIM + k0 + a_c0 * 8);
        rA[1] = *(const uint4*)(g_rh + (bm + a_r1) * P_DIM + k0 + a_c1 * 8);
        rB = *(const uint4*)(g_cbh + (size_t)(bn + b_r) * P_DIM + k0 + b_c * 8);
    };
    auto store_tile = [&]() {
        *(uint4*)&Ah[a_r0][a_c0 * 8] = rA[0];
        *(uint4*)&Ah[a_r1][a_c1 * 8] = rA[1];
        *(uint4*)&Bh[b_r][b_c * 8] = rB;
    };

    load_tile(0);
    for (int kc = 0; kc < P_DIM / 32; kc++) {
        store_tile();
        __syncthreads();
        if (kc + 1 < P_DIM / 32) load_tile(kc + 1);
#pragma unroll
        for (int ks = 0; ks < 2; ks++) {
            const int kk = ks * 16;
            uint32_t bf[4][2];
#pragma unroll
            for (int p = 0; p < 2; p++) {
                const int n0 = warp_n * 32 + p * 16;
                uint32_t off = (uint32_t)((n0 + ((g >> 1) << 3) + lr) * 40 + kk + ((g & 1) << 3)) * 2;
                uint32_t t[4];
                ldm4(t, sBh + off);
                bf[p * 2][0] = t[0]; bf[p * 2][1] = t[1];
                bf[p * 2 + 1][0] = t[2]; bf[p * 2 + 1][1] = t[3];
            }
#pragma unroll
            for (int mt = 0; mt < 2; mt++) {
                const int m0 = warp_m * 32 + mt * 16;
                uint32_t aoff = (uint32_t)((m0 + ((g & 1) << 3) + lr) * 40 + kk + ((g >> 1) << 3)) * 2;
                uint32_t ah[4];
                ldm4(ah, sAh + aoff);
#pragma unroll
                for (int nt = 0; nt < 4; nt++) mma_fp16(acc[mt][nt], ah, bf[nt]);
            }
        }
        __syncthreads();
    }
#pragma unroll
    for (int mt = 0; mt < 2; mt++) {
        const size_t row = bm + warp_m * 32 + mt * 16 + (lane >> 2);
#pragma unroll
        for (int nt = 0; nt < 4; nt++) {
            const int col = bn + warp_n * 32 + nt * 8 + ((lane & 3) << 1);
            *(float2*)(g_S + row * KT + col) = make_float2(acc[mt][nt][0], acc[mt][nt][1]);
            *(float2*)(g_S + (row + 8) * KT + col) = make_float2(acc[mt][nt][2], acc[mt][nt][3]);
        }
    }
}

// ------------------- cascade pick + inline ssr(fp16) + inline compact -----------------
__device__ __forceinline__ void top2_reduce(float& m1, float& m2, int& i1) {
#pragma unroll
    for (int o = 16; o; o >>= 1) {
        float om1 = __shfl_xor_sync(0xffffffffu, m1, o);
        int   oi1 = __shfl_xor_sync(0xffffffffu, i1, o);
        float om2 = __shfl_xor_sync(0xffffffffu, m2, o);
        if (om1 < m1 || (om1 == m1 && oi1 < i1)) { m2 = fminf(m1, om2); m1 = om1; i1 = oi1; }
        else m2 = fminf(m2, om1);
    }
}

__global__ __launch_bounds__(256) void k_pickcas(float* __restrict__ out_idxf) {
    __shared__ float ssq_s[KT];
    for (int i = threadIdx.x; i < KT; i += 256) ssq_s[i] = g_ssq[i];
    __syncthreads();
    const int warp = threadIdx.x >> 5, lane = threadIdx.x & 31;
    const int t = blockIdx.x * 8 + warp;
    const float* Srow = g_S + (size_t)t * KT;

    // ssr from fp16 zproj (loss only; tolerance 1e-3)
    float s;
    {
        uint4 rv = *(const uint4*)(g_rh + (size_t)t * P_DIM + lane * 8);
        const __half2* hp = (const __half2*)&rv;
        float acc = 0.f;
#pragma unroll
        for (int q = 0; q < 4; q++) {
            float2 f = __half22float2(hp[q]);
            acc += f.x * f.x + f.y * f.y;
        }
#pragma unroll
        for (int o = 16; o; o >>= 1) acc += __shfl_xor_sync(0xffffffffu, acc, o);
        s = acc;
    }

    float m1 = CUDART_INF_F, m2 = CUDART_INF_F; int i1 = 0x7fffffff;
#pragma unroll
    for (int kc = 0; kc < 2; kc++) {
        int j = kc * 32 + lane;
        float d = ssq_s[j] - 2.0f * Srow[j];
        if (d < m1) { m2 = m1; m1 = d; i1 = j; } else m2 = fminf(m2, d);
    }
    top2_reduce(m1, m2, i1);
    const int i0 = i1; const float mv0 = m1, gap0 = m2 - m1;

    const float* g01 = g_G01 + i0 * KC1;
    m1 = CUDART_INF_F; m2 = CUDART_INF_F; i1 = 0x7fffffff;
#pragma unroll
    for (int kc = 0; kc < 4; kc++) {
        int j = kc * 32 + lane;
        float d = ssq_s[KC0 + j] - 2.0f * (Srow[KC0 + j] - g01[j]);
        if (d < m1) { m2 = m1; m1 = d; i1 = j; } else m2 = fminf(m2, d);
    }
    top2_reduce(m1, m2, i1);
    const int idx1 = i1; const float mv1 = m1, gap1 = m2 - m1;

    const float* g02 = g_G02 + i0 * KC2;
    const float* g12 = g_G12 + idx1 * KC2;
    m1 = CUDART_INF_F; m2 = CUDART_INF_F; i1 = 0x7fffffff;
#pragma unroll
    for (int kc = 0; kc < 8; kc++) {
        int j = kc * 32 + lane;
        float d = ssq_s[KC0 + KC1 + j] - 2.0f * (Srow[KC0 + KC1 + j] - g02[j] - g12[j]);
        if (d < m1) { m2 = m1; m1 = d; i1 = j; } else m2 = fminf(m2, d);
    }
    top2_reduce(m1, m2, i1);
    const int idx2 = i1; const float mv2 = m1, gap2 = m2 - m1;

    if (lane == 0) {
        g_idx[t] = i0; g_idx[T_TOK + t] = idx1; g_idx[2 * T_TOK + t] = idx2;
        out_idxf[t] = (float)i0;
        out_idxf[T_TOK + t] = (float)idx1;
        out_idxf[2 * T_TOK + t] = (float)idx2;
        if (gap0 < TAU || gap1 < TAU || gap2 < TAU)
            g_flaglist[atomicAdd(&g_flagcnt[0], 1)] = t;
        g_losstok[t] = 3.f * s + 3.f * mv0 + 2.f * mv1 + mv2;
    }
}

// ------------------- fixup A v2: exact zproj, 64 tokens/CTA, 8x8 per thread -----------
__global__ __launch_bounds__(256) void k_fixA(const float* __restrict__ z,
                                              const float* __restrict__ Win,
                                              const float* __restrict__ bin) {
    extern __shared__ char sm[];
    float* zsm = (float*)sm;                 // [64][68]
    float* Wsm = (float*)(sm + 64 * 68 * 4); // [64][256]
    __shared__ int tl[64];
    const int tid = threadIdx.x;
    const int cnt = g_flagcnt[0];
    if (cnt == 0) return;

    for (int base = blockIdx.x * 64; base < cnt; base += gridDim.x * 64) {
        if (tid < 64) tl[tid] = g_flaglist[min(base + tid, cnt - 1)];
        __syncthreads();
        const int tg = tid >> 5, cg = tid & 31;   // token octet, col octet
        float acc[8][8];
#pragma unroll
        for (int a = 0; a < 8; a++)
#pragma unroll
            for (int b = 0; b < 8; b++) acc[a][b] = 0.f;

        for (int kc = 0; kc < D_DIM / 64; kc++) {
#pragma unroll
            for (int q = 0; q < 4; q++) {         // z: 1024 float4
                int i = tid + q * 256;
                int sT = i >> 4, c4 = i & 15;
                *(float4*)(zsm + sT * 68 + c4 * 4) =
                    *(const float4*)(z + (size_t)tl[sT] * D_DIM + kc * 64 + c4 * 4);
            }
#pragma unroll
            for (int q = 0; q < 16; q++) {        // W: 4096 float4
                int i = tid + q * 256;
                int k = i >> 6, c4 = i & 63;
                *(float4*)(Wsm + k * 256 + c4 * 4) =
                    *(const float4*)(Win + (size_t)(kc * 64 + k) * P_DIM + c4 * 4);
            }
            __syncthreads();
            for (int k = 0; k < 64; k++) {
                float4 w0 = *(const float4*)(Wsm + k * 256 + cg * 8);
                float4 w1 = *(const float4*)(Wsm + k * 256 + cg * 8 + 4);
                float wv[8] = {w0.x, w0.y, w0.z, w0.w, w1.x, w1.y, w1.z, w1.w};
#pragma unroll
                for (int a = 0; a < 8; a++) {
                    float zv = zsm[(tg * 8 + a) * 68 + k];
#pragma unroll
                    for (int b = 0; b < 8; b++)
                        acc[a][b] = __fmaf_rn(zv, wv[b], acc[a][b]);
                }
            }
            __syncthreads();
        }
#pragma unroll
        for (int a = 0; a < 8; a++) {
            int sT = tg * 8 + a;
            if (base + sT < cnt) {
                float* dst = g_r + (size_t)tl[sT] * P_DIM;
#pragma unroll
                for (int b = 0; b < 8; b++)
                    dst[cg * 8 + b] = __fadd_rn(acc[a][b], bin[cg * 8 + b]);
            }
        }
        __syncthreads();
    }
}

// ------------------- fixup B: windowed exact replay (R14-proven) ----------------------
__global__ __launch_bounds__(256) void k_fixB(const float* __restrict__ e0,
                                              const float* __restrict__ e1,
                                              const float* __restrict__ e2,
                                              float* __restrict__ out_idxf) {
    __shared__ float r_sm[8][264];
    __shared__ int cand[8][64];
    __shared__ float ssq_sm[KT];
    const int tid = threadIdx.x, warp = tid >> 5, lane = tid & 31;
    const int cnt = g_flagcnt[0];
    if (cnt == 0) return;
    for (int i = tid; i < KT; i += 256) ssq_sm[i] = g_ssq[i];
    __syncthreads();

    const float* cbl_[3] = {e0, e1, e2};
    const int Kl[3] = {KC0, KC1, KC2};
    const int offl[3] = {0, KC0, KC0 + KC1};

    for (int base = blockIdx.x * 8 + warp; base < cnt; base += gridDim.x * 8) {
        const int t = g_flaglist[base];
#pragma unroll
        for (int k = 0; k < 8; k++)
            r_sm[warp][lane + 32 * k] = g_r[(size_t)t * P_DIM + lane + 32 * k];
        __syncwarp();
        float ssr;
        if (lane == 0) {
            float s = 0.f;
            for (int p = 0; p < P_DIM; p++)
                s = __fadd_rn(s, __fmul_rn(r_sm[warp][p], r_sm[warp][p]));
            ssr = s;
        }
        ssr = __shfl_sync(0xffffffffu, ssr, 0);

        const float* Srow = g_S + (size_t)t * KT;
        int idxs[3];
        double lsd = 0.0;
        int i0 = 0, i1e = 0;
        for (int lvl = 0; lvl < 3; lvl++) {
            const int K = Kl[lvl], off = offl[lvl];
            const float* cb = cbl_[lvl];
            const float* gr0 = (lvl == 1) ? (g_G01 + i0 * KC1)
                             : (lvl == 2) ? (g_G02 + i0 * KC2) : nullptr;
            const float* gr1 = (lvl == 2) ? (g_G12 + i1e * KC2) : nullptr;
            float dd[8];
            float m1 = CUDART_INF_F;
            for (int kc = 0; kc < K / 32; kc++) {
                int j = kc * 32 + lane;
                float sv = Srow[off + j];
                if (gr0) sv -= gr0[j];
                if (gr1) sv -= gr1[j];
                float d = ssq_sm[off + j] - 2.0f * sv;
                dd[kc] = d;
                m1 = fminf(m1, d);
            }
#pragma unroll
            for (int o = 16; o; o >>= 1) m1 = fminf(m1, __shfl_xor_sync(0xffffffffu, m1, o));
            const float thr = m1 + TAU;
            int n = 0;
            for (int kc = 0; kc < K / 32; kc++) {
                unsigned msk = __ballot_sync(0xffffffffu, dd[kc] <= thr);
                if ((dd[kc] <= thr)) {
                    int pos = n + __popc(msk & ((1u << lane) - 1));
                    if (pos < 64) cand[warp][pos] = kc * 32 + lane;
                }
                n += __popc(msk);
            }
            if (n > 64) n = 64;
            __syncwarp();
            float best = CUDART_INF_F; int bi = 0x7fffffff;
            for (int b0 = 0; b0 < n; b0 += 32) {
                int ci = b0 + lane;
                float dex = CUDART_INF_F; int jj = 0x7fffffff;
                if (ci < n) {
                    jj = cand[warp][ci];
                    const float* er = cb + (size_t)jj * P_DIM;
                    float a = 0.f;
                    for (int p = 0; p < P_DIM; p++)
                        a = __fmaf_rn(r_sm[warp][p], er[p], a);
                    dex = __fadd_rn(__fsub_rn(ssr, 2.0f * a), g_ssq[off + jj]);
                }
                float bm = dex; int bj = jj;
#pragma unroll
                for (int o = 16; o; o >>= 1) {
                    float od = __shfl_xor_sync(0xffffffffu, bm, o);
                    int   oi = __shfl_xor_sync(0xffffffffu, bj, o);
                    if (od < bm || (od == bm && oi < bj)) { bm = od; bj = oi; }
                }
                if (bm < best || (bm == best && bj < bi)) { best = bm; bi = bj; }
            }
            idxs[lvl] = bi;
            if (lvl == 0) i0 = bi; else if (lvl == 1) i1e = bi;
            const float* er = cb + (size_t)bi * P_DIM;
            double lp = 0.0;
#pragma unroll
            for (int k = 0; k < 8; k++) {
                int p = lane + 32 * k;
                float nv = __fsub_rn(r_sm[warp][p], er[p]);
                r_sm[warp][p] = nv;
                lp += (double)nv * (double)nv;
            }
            __syncwarp();
#pragma unroll
            for (int o = 16; o; o >>= 1) lp += __shfl_xor_sync(0xffffffffu, lp, o);
            lsd += lp;
            if (lvl < 2) {
                if (lane == 0) {
                    float s = 0.f;
                    for (int p = 0; p < P_DIM; p++)
                        s = __fadd_rn(s, __fmul_rn(r_sm[warp][p], r_sm[warp][p]));
                    ssr = s;
                }
                ssr = __shfl_sync(0xffffffffu, ssr, 0);
            }
        }
        if (lane == 0) {
            g_idx[t] = idxs[0]; g_idx[T_TOK + t] = idxs[1]; g_idx[2 * T_TOK + t] = idxs[2];
            out_idxf[t] = (float)idxs[0];
            out_idxf[T_TOK + t] = (float)idxs[1];
            out_idxf[2 * T_TOK + t] = (float)idxs[2];
            g_losstok[t] = (float)lsd;
        }
        __syncwarp();
    }
}

// ------------------- loss reduce -------------------
__global__ __launch_bounds__(256) void k_lossred(float* __restrict__ out_loss) {
    __shared__ double smm[256];
    double s = 0.0;
    for (int i = threadIdx.x; i < T_TOK; i += 256) s += (double)g_losstok[i];
    smm[threadIdx.x] = s;
    __syncthreads();
    for (int o = 128; o; o >>= 1) {
        if (threadIdx.x < o) smm[threadIdx.x] += smm[threadIdx.x + o];
        __syncthreads();
    }
    if (threadIdx.x == 0)
        *out_loss = (float)(smm[0] * (0.25 / (3.0 * (double)T_TOK * (double)P_DIM)));
}

// ------------------- EW = emb_cat @ W_out -------------------
__global__ __launch_bounds__(256) void k_ew(const float* __restrict__ e0,
                                            const float* __restrict__ e1,
                                            const float* __restrict__ e2,
                                            const float* __restrict__ Wout) {
    __shared__ float a[8][P_DIM];
    const int rbase = blockIdx.x * 8;
    for (int i = threadIdx.x; i < 8 * P_DIM; i += 256) {
        int r = rbase + i / P_DIM, p = i % P_DIM;
        const float* s = (r < KC0) ? (e0 + (size_t)r * P_DIM)
                       : (r < KC0 + KC1) ? (e1 + (size_t)(r - KC0) * P_DIM)
                                         : (e2 + (size_t)(r - KC0 - KC1) * P_DIM);
        a[i / P_DIM][p] = s[p];
    }
    __syncthreads();
    for (int c = threadIdx.x; c < D_DIM; c += 256) {
        float acc[8] = {0.f, 0.f, 0.f, 0.f, 0.f, 0.f, 0.f, 0.f};
        for (int p = 0; p < P_DIM; p++) {
            float w = Wout[(size_t)p * D_DIM + c];
#pragma unroll
            for (int r = 0; r < 8; r++) acc[r] = __fmaf_rn(a[r][p], w, acc[r]);
        }
#pragma unroll
        for (int r = 0; r < 8; r++) g_EW[(size_t)(rbase + r) * D_DIM + c] = acc[r];
    }
}

// ------------------- output gather -------------------
__global__ __launch_bounds__(352) void k_out(const float* __restrict__ bout,
                                             float* __restrict__ out) {
    const int t = blockIdx.x;
    const int i0 = g_idx[t], i1 = g_idx[T_TOK + t], i2 = g_idx[2 * T_TOK + t];
    const float4* r0 = (const float4*)(g_EW + (size_t)i0 * D_DIM);
    const float4* r1 = (const float4*)(g_EW + (size_t)(KC0 + i1) * D_DIM);
    const float4* r2 = (const float4*)(g_EW + (size_t)(KC0 + KC1 + i2) * D_DIM);
    const float4* bb = (const float4*)bout;
    float4* o = (float4*)(out + (size_t)t * D_DIM);
    const int c = threadIdx.x;
    float4 a = r0[c], b = r1[c], cc = r2[c], d = bb[c];
    o[c] = make_float4(a.x + b.x + cc.x + d.x, a.y + b.y + cc.y + d.y,
                       a.z + b.z + cc.z + d.z, a.w + b.w + cc.w + d.w);
}

// ------------------- launch -------------------
extern "C" void kernel_launch(void* const* d_in, const int* in_sizes, int n_in,
                              void* d_out, int out_size) {
    const float* z     = (const float*)d_in[0];
    const float* W_in  = (const float*)d_in[1];
    const float* b_in  = (const float*)d_in[2];
    const float* W_out = (const float*)d_in[3];
    const float* b_out = (const float*)d_in[4];
    const float* e0    = (const float*)d_in[5];
    const float* e1    = (const float*)d_in[6];
    const float* e2    = (const float*)d_in[7];

    float* out      = (float*)d_out;
    float* out_idxf = out + (size_t)T_TOK * D_DIM;
    float* out_loss = out_idxf + 3 * T_TOK;

    const int FIXA_SMEM = 64 * 68 * 4 + 64 * 256 * 4;
    cudaFuncSetAttribute(k_fixA, cudaFuncAttributeMaxDynamicSharedMemorySize, FIXA_SMEM);

    k_wprep<<<dim3(D_DIM / 32, P_DIM / 32), 256>>>(W_in);
    k_cbprep<<<KT, 256>>>(e0, e1, e2);
    k_zero1<<<1, 32>>>();
    k_gemm1_mma<<<T_TOK / 128, 512>>>(z, b_in);        // 4th launch -> profiled

    k_tables<<<7168, 256>>>(e0, e1, e2);
    k_ew<<<KT / 8, 256>>>(e0, e1, e2, W_out);

    k_gemmS_mma<<<dim3(KT / 64, T_TOK / 128), 256>>>();
    k_pickcas<<<T_TOK / 8, 256>>>(out_idxf);

    k_fixA<<<256, 256, FIXA_SMEM>>>(z, W_in, b_in);
    k_fixB<<<512, 256>>>(e0, e1, e2, out_idxf);

    k_lossred<<<1, 256>>>(out_loss);
    k_out<<<T_TOK, 352>>>(b_out, out);
}

// round 17
// speedup vs baseline: 1.3451x; 1.2595x over previous
#include <cuda_runtime.h>
#include <cuda_fp16.h>
#include <math_constants.h>
#include <cstdint>

#define T_TOK 32768
#define D_DIM 1408
#define P_DIM 256
#define KC0 64
#define KC1 128
#define KC2 256
#define KT  448
#define TAU 1e-2f

// ------------------- device scratch -------------------
static __device__ float  g_r[(size_t)T_TOK * P_DIM];      // approx zproj; fixA overwrites flagged rows with EXACT zproj
static __device__ float  g_S[(size_t)T_TOK * KT];         // approx scores (preserved for fixB windowing)
static __device__ float  g_ssq[KT];
static __device__ float  g_ssr[T_TOK];
static __device__ float  g_G01[KC0 * KC1];
static __device__ float  g_G02[KC0 * KC2];
static __device__ float  g_G12[KC1 * KC2];
static __device__ float  g_EW[(size_t)KT * D_DIM];
static __device__ int    g_idx[3 * T_TOK];
static __device__ float  g_losstok[T_TOK];
static __device__ int    g_flagged[T_TOK];
static __device__ int    g_flagcnt[1];
static __device__ int    g_flaglist[T_TOK];
static __device__ __half g_WhT[(size_t)P_DIM * D_DIM];    // W_in^T fp16 [256][1408]
static __device__ __half g_rh[(size_t)T_TOK * P_DIM];     // zproj fp16
static __device__ __half g_cbh[KT * P_DIM];               // codebooks fp16 [448][256]

// ------------------- helpers -------------------
__device__ __forceinline__ uint32_t smem_u32(const void* p) {
    uint32_t a;
    asm("{ .reg .u64 t; cvta.to.shared.u64 t, %1; cvt.u32.u64 %0, t; }" : "=r"(a) : "l"(p));
    return a;
}
__device__ __forceinline__ void ldm4(uint32_t r[4], uint32_t a) {
    asm volatile("ldmatrix.sync.aligned.m8n8.x4.shared.b16 {%0,%1,%2,%3}, [%4];"
                 : "=r"(r[0]), "=r"(r[1]), "=r"(r[2]), "=r"(r[3]) : "r"(a));
}
__device__ __forceinline__ void mma_fp16(float c[4], const uint32_t a[4], const uint32_t b[2]) {
    asm volatile("mma.sync.aligned.m16n8k16.row.col.f32.f16.f16.f32 "
                 "{%0,%1,%2,%3}, {%4,%5,%6,%7}, {%8,%9}, {%0,%1,%2,%3};"
                 : "+f"(c[0]), "+f"(c[1]), "+f"(c[2]), "+f"(c[3])
                 : "r"(a[0]), "r"(a[1]), "r"(a[2]), "r"(a[3]), "r"(b[0]), "r"(b[1]));
}

// ------------------- zero counter -------------------
__global__ void k_zero1() { if (threadIdx.x == 0) g_flagcnt[0] = 0; }

// ------------------- W_in -> fp16 transpose -------------------
__global__ __launch_bounds__(256) void k_wprep(const float* __restrict__ Win) {
    __shared__ float tile[32][33];
    const int r0 = blockIdx.x * 32, c0 = blockIdx.y * 32;
    const int tx = threadIdx.x & 31, ty = threadIdx.x >> 5;
    for (int rr = ty; rr < 32; rr += 8)
        tile[rr][tx] = Win[(size_t)(r0 + rr) * P_DIM + c0 + tx];
    __syncthreads();
    for (int rr = ty; rr < 32; rr += 8)
        g_WhT[(size_t)(c0 + rr) * D_DIM + r0 + tx] = __float2half_rn(tile[tx][rr]);
}

// ------------------- codebooks -> fp16 -------------------
__global__ __launch_bounds__(256) void k_cbprep(const float* __restrict__ e0,
                                                const float* __restrict__ e1,
                                                const float* __restrict__ e2) {
    const int row = blockIdx.x;
    const float* src = (row < KC0) ? (e0 + (size_t)row * P_DIM)
                     : (row < KC0 + KC1) ? (e1 + (size_t)(row - KC0) * P_DIM)
                                         : (e2 + (size_t)(row - KC0 - KC1) * P_DIM);
    g_cbh[row * P_DIM + threadIdx.x] = __float2half_rn(src[threadIdx.x]);
}

// ------------------- ssq (exact fp32 sequential order) -------------------
__global__ __launch_bounds__(256) void k_ssqE(const float* __restrict__ e0,
                                              const float* __restrict__ e1,
                                              const float* __restrict__ e2) {
    __shared__ float buf[8][260];
    const int warp = threadIdx.x >> 5, lane = threadIdx.x & 31;
    const int r = blockIdx.x * 8 + warp;
    if (r >= KT) return;
    const float* src = (r < KC0) ? (e0 + (size_t)r * P_DIM)
                     : (r < KC0 + KC1) ? (e1 + (size_t)(r - KC0) * P_DIM)
                                       : (e2 + (size_t)(r - KC0 - KC1) * P_DIM);
#pragma unroll
    for (int k = 0; k < 8; k++) buf[warp][lane + 32 * k] = src[lane + 32 * k];
    __syncwarp();
    if (lane == 0) {
        float s = 0.f;
        for (int p = 0; p < P_DIM; p++) s = __fadd_rn(s, __fmul_rn(buf[warp][p], buf[warp][p]));
        g_ssq[r] = s;
    }
}

// ------------------- Gram tables -------------------
__global__ __launch_bounds__(256) void k_tables(const float* __restrict__ e0,
                                                const float* __restrict__ e1,
                                                const float* __restrict__ e2) {
    int gw = (blockIdx.x * 256 + threadIdx.x) >> 5;
    int lane = threadIdx.x & 31;
    if (gw >= 57344) return;
    const float *a, *b;
    float* dst;
    if (gw < 8192) {
        a = e0 + (size_t)(gw >> 7) * P_DIM;
        b = e1 + (size_t)(gw & 127) * P_DIM;
        dst = g_G01 + gw;
    } else if (gw < 24576) {
        int id = gw - 8192;
        a = e0 + (size_t)(id >> 8) * P_DIM;
        b = e2 + (size_t)(id & 255) * P_DIM;
        dst = g_G02 + id;
    } else {
        int id = gw - 24576;
        a = e1 + (size_t)(id >> 8) * P_DIM;
        b = e2 + (size_t)(id & 255) * P_DIM;
        dst = g_G12 + id;
    }
    float s = 0.f;
#pragma unroll
    for (int k = 0; k < 8; k++) s += a[lane + 32 * k] * b[lane + 32 * k];
#pragma unroll
    for (int o = 16; o; o >>= 1) s += __shfl_xor_sync(0xffffffffu, s, o);
    if (lane == 0) *dst = s;
}

// ------------------- GEMM1: inline-cvt fp16 (ONLY delta vs R14), writes g_r + g_rh ----
__global__ __launch_bounds__(512) void k_gemm1_mma(const float* __restrict__ z,
                                                   const float* __restrict__ bin) {
    __shared__ __half Ah[128][40], Bh[256][40];
    const int tid = threadIdx.x, wid = tid >> 5, lane = tid & 31;
    const int warp_m = wid >> 3, warp_n = wid & 7;
    const size_t bm = (size_t)blockIdx.x * 128;
    const uint32_t sAh = smem_u32(Ah), sBh = smem_u32(Bh);
    const int g = lane >> 3, lr = lane & 7;
    const int a_s0 = (tid * 2) >> 3, a_c0 = (tid * 2) & 7;
    const int a_s1 = (tid * 2 + 1) >> 3, a_c1 = (tid * 2 + 1) & 7;
    const int b_n0 = (tid * 2) >> 2, b_c0 = (tid * 2) & 3;
    const int b_n1 = (tid * 2 + 1) >> 2, b_c1 = (tid * 2 + 1) & 3;

    float acc[4][4][4];
#pragma unroll
    for (int mt = 0; mt < 4; mt++)
#pragma unroll
        for (int nt = 0; nt < 4; nt++)
#pragma unroll
            for (int q = 0; q < 4; q++) acc[mt][nt][q] = 0.f;

    float4 az[2];
    uint4 rB[2];
    auto load_tile = [&](int kc) {
        const int k0 = kc * 32;
        az[0] = *(const float4*)(z + (bm + a_s0) * D_DIM + k0 + a_c0 * 4);
        az[1] = *(const float4*)(z + (bm + a_s1) * D_DIM + k0 + a_c1 * 4);
        rB[0] = *(const uint4*)(g_WhT + (size_t)b_n0 * D_DIM + k0 + b_c0 * 8);
        rB[1] = *(const uint4*)(g_WhT + (size_t)b_n1 * D_DIM + k0 + b_c1 * 8);
    };
    auto store_tile = [&]() {
        __half2 p0 = __floats2half2_rn(az[0].x, az[0].y);
        __half2 p1 = __floats2half2_rn(az[0].z, az[0].w);
        *(uint2*)&Ah[a_s0][a_c0 * 4] = make_uint2(*(uint32_t*)&p0, *(uint32_t*)&p1);
        p0 = __floats2half2_rn(az[1].x, az[1].y);
        p1 = __floats2half2_rn(az[1].z, az[1].w);
        *(uint2*)&Ah[a_s1][a_c1 * 4] = make_uint2(*(uint32_t*)&p0, *(uint32_t*)&p1);
        *(uint4*)&Bh[b_n0][b_c0 * 8] = rB[0];
        *(uint4*)&Bh[b_n1][b_c1 * 8] = rB[1];
    };

    load_tile(0);
    const int NK = D_DIM / 32;
    for (int kc = 0; kc < NK; kc++) {
        store_tile();
        __syncthreads();
        if (kc + 1 < NK) load_tile(kc + 1);
#pragma unroll
        for (int ks = 0; ks < 2; ks++) {
            const int kk = ks * 16;
            uint32_t bf[4][2];
#pragma unroll
            for (int p = 0; p < 2; p++) {
                const int n0 = warp_n * 32 + p * 16;
                uint32_t off = (uint32_t)((n0 + ((g >> 1) << 3) + lr) * 40 + kk + ((g & 1) << 3)) * 2;
                uint32_t t[4];
                ldm4(t, sBh + off);
                bf[p * 2][0] = t[0]; bf[p * 2][1] = t[1];
                bf[p * 2 + 1][0] = t[2]; bf[p * 2 + 1][1] = t[3];
            }
#pragma unroll
            for (int mt = 0; mt < 4; mt++) {
                const int m0 = warp_m * 64 + mt * 16;
                uint32_t aoff = (uint32_t)((m0 + ((g & 1) << 3) + lr) * 40 + kk + ((g >> 1) << 3)) * 2;
                uint32_t ah[4];
                ldm4(ah, sAh + aoff);
#pragma unroll
                for (int nt = 0; nt < 4; nt++) mma_fp16(acc[mt][nt], ah, bf[nt]);
            }
        }
        __syncthreads();
    }
    // epilogue: + bias -> g_r fp32 and g_rh fp16 (exactly as R14)
#pragma unroll
    for (int mt = 0; mt < 4; mt++) {
        const size_t row = bm + warp_m * 64 + mt * 16 + (lane >> 2);
#pragma unroll
        for (int nt = 0; nt < 4; nt++) {
            const int col = warp_n * 32 + nt * 8 + ((lane & 3) << 1);
            float b0 = bin[col], b1 = bin[col + 1];
            float v0 = acc[mt][nt][0] + b0, v1 = acc[mt][nt][1] + b1;
            float v2 = acc[mt][nt][2] + b0, v3 = acc[mt][nt][3] + b1;
            *(float2*)(g_r + row * P_DIM + col) = make_float2(v0, v1);
            *(float2*)(g_r + (row + 8) * P_DIM + col) = make_float2(v2, v3);
            __half2 p = __floats2half2_rn(v0, v1);
            *(uint32_t*)(g_rh + row * P_DIM + col) = *(uint32_t*)&p;
            p = __floats2half2_rn(v2, v3);
            *(uint32_t*)(g_rh + (row + 8) * P_DIM + col) = *(uint32_t*)&p;
        }
    }
}

// ------------------- GEMMS: fp16 single-product (R14-proven) -------------------
__global__ __launch_bounds__(256) void k_gemmS_mma() {
    __shared__ __half Ah[128][40], Bh[64][40];
    const int tid = threadIdx.x, wid = tid >> 5, lane = tid & 31;
    const int warp_m = wid >> 1, warp_n = wid & 1;
    const size_t bm = (size_t)blockIdx.y * 128;
    const int bn = blockIdx.x * 64;
    const uint32_t sAh = smem_u32(Ah), sBh = smem_u32(Bh);
    const int g = lane >> 3, lr = lane & 7;
    const int a_r0 = (tid * 2) >> 2, a_c0 = (tid * 2) & 3;
    const int a_r1 = (tid * 2 + 1) >> 2, a_c1 = (tid * 2 + 1) & 3;
    const int b_r = tid >> 2, b_c = tid & 3;

    float acc[2][4][4];
#pragma unroll
    for (int mt = 0; mt < 2; mt++)
#pragma unroll
        for (int nt = 0; nt < 4; nt++)
#pragma unroll
            for (int q = 0; q < 4; q++) acc[mt][nt][q] = 0.f;

    uint4 rA[2], rB;
    auto load_tile = [&](int kc) {
        const int k0 = kc * 32;
        rA[0] = *(const uint4*)(g_rh + (bm + a_r0) * P_DIM + k0 + a_c0 * 8);
        rA[1] = *(const uint4*)(g_rh + (bm + a_r1) * P_DIM + k0 + a_c1 * 8);
        rB = *(const uint4*)(g_cbh + (size_t)(bn + b_r) * P_DIM + k0 + b_c * 8);
    };
    auto store_tile = [&]() {
        *(uint4*)&Ah[a_r0][a_c0 * 8] = rA[0];
        *(uint4*)&Ah[a_r1][a_c1 * 8] = rA[1];
        *(uint4*)&Bh[b_r][b_c * 8] = rB;
    };

    load_tile(0);
    for (int kc = 0; kc < P_DIM / 32; kc++) {
        store_tile();
        __syncthreads();
        if (kc + 1 < P_DIM / 32) load_tile(kc + 1);
#pragma unroll
        for (int ks = 0; ks < 2; ks++) {
            const int kk = ks * 16;
            uint32_t bf[4][2];
#pragma unroll
            for (int p = 0; p < 2; p++) {
                const int n0 = warp_n * 32 + p * 16;
                uint32_t off = (uint32_t)((n0 + ((g >> 1) << 3) + lr) * 40 + kk + ((g & 1) << 3)) * 2;
                uint32_t t[4];
                ldm4(t, sBh + off);
                bf[p * 2][0] = t[0]; bf[p * 2][1] = t[1];
                bf[p * 2 + 1][0] = t[2]; bf[p * 2 + 1][1] = t[3];
            }
#pragma unroll
            for (int mt = 0; mt < 2; mt++) {
                const int m0 = warp_m * 32 + mt * 16;
                uint32_t aoff = (uint32_t)((m0 + ((g & 1) << 3) + lr) * 40 + kk + ((g >> 1) << 3)) * 2;
                uint32_t ah[4];
                ldm4(ah, sAh + aoff);
#pragma unroll
                for (int nt = 0; nt < 4; nt++) mma_fp16(acc[mt][nt], ah, bf[nt]);
            }
        }
        __syncthreads();
    }
#pragma unroll
    for (int mt = 0; mt < 2; mt++) {
        const size_t row = bm + warp_m * 32 + mt * 16 + (lane >> 2);
#pragma unroll
        for (int nt = 0; nt < 4; nt++) {
            const int col = bn + warp_n * 32 + nt * 8 + ((lane & 3) << 1);
            *(float2*)(g_S + row * KT + col) = make_float2(acc[mt][nt][0], acc[mt][nt][1]);
            *(float2*)(g_S + (row + 8) * KT + col) = make_float2(acc[mt][nt][2], acc[mt][nt][3]);
        }
    }
}

// ------------------- ssr (fp32, as R14) -------------------
__global__ __launch_bounds__(256) void k_ssr() {
    const int warp = threadIdx.x >> 5, lane = threadIdx.x & 31;
    const size_t t = (size_t)blockIdx.x * 8 + warp;
    const float* rr = g_r + t * P_DIM;
    float s = 0.f;
#pragma unroll
    for (int k = 0; k < 8; k++) { float v = rr[lane + 32 * k]; s += v * v; }
#pragma unroll
    for (int o = 16; o; o >>= 1) s += __shfl_xor_sync(0xffffffffu, s, o);
    if (lane == 0) g_ssr[t] = s;
}

// ------------------- cascade pick (R14) -------------------
__device__ __forceinline__ void top2_reduce(float& m1, float& m2, int& i1) {
#pragma unroll
    for (int o = 16; o; o >>= 1) {
        float om1 = __shfl_xor_sync(0xffffffffu, m1, o);
        int   oi1 = __shfl_xor_sync(0xffffffffu, i1, o);
        float om2 = __shfl_xor_sync(0xffffffffu, m2, o);
        if (om1 < m1 || (om1 == m1 && oi1 < i1)) { m2 = fminf(m1, om2); m1 = om1; i1 = oi1; }
        else m2 = fminf(m2, om1);
    }
}

__global__ __launch_bounds__(256) void k_pickcas(float* __restrict__ out_idxf) {
    __shared__ float ssq_s[KT];
    for (int i = threadIdx.x; i < KT; i += 256) ssq_s[i] = g_ssq[i];
    __syncthreads();
    const int warp = threadIdx.x >> 5, lane = threadIdx.x & 31;
    const int t = blockIdx.x * 8 + warp;
    const float* Srow = g_S + (size_t)t * KT;

    float m1 = CUDART_INF_F, m2 = CUDART_INF_F; int i1 = 0x7fffffff;
#pragma unroll
    for (int kc = 0; kc < 2; kc++) {
        int j = kc * 32 + lane;
        float d = ssq_s[j] - 2.0f * Srow[j];
        if (d < m1) { m2 = m1; m1 = d; i1 = j; } else m2 = fminf(m2, d);
    }
    top2_reduce(m1, m2, i1);
    const int i0 = i1; const float mv0 = m1, gap0 = m2 - m1;

    const float* g01 = g_G01 + i0 * KC1;
    m1 = CUDART_INF_F; m2 = CUDART_INF_F; i1 = 0x7fffffff;
#pragma unroll
    for (int kc = 0; kc < 4; kc++) {
        int j = kc * 32 + lane;
        float d = ssq_s[KC0 + j] - 2.0f * (Srow[KC0 + j] - g01[j]);
        if (d < m1) { m2 = m1; m1 = d; i1 = j; } else m2 = fminf(m2, d);
    }
    top2_reduce(m1, m2, i1);
    const int idx1 = i1; const float mv1 = m1, gap1 = m2 - m1;

    const float* g02 = g_G02 + i0 * KC2;
    const float* g12 = g_G12 + idx1 * KC2;
    m1 = CUDART_INF_F; m2 = CUDART_INF_F; i1 = 0x7fffffff;
#pragma unroll
    for (int kc = 0; kc < 8; kc++) {
        int j = kc * 32 + lane;
        float d = ssq_s[KC0 + KC1 + j] - 2.0f * (Srow[KC0 + KC1 + j] - g02[j] - g12[j]);
        if (d < m1) { m2 = m1; m1 = d; i1 = j; } else m2 = fminf(m2, d);
    }
    top2_reduce(m1, m2, i1);
    const int idx2 = i1; const float mv2 = m1, gap2 = m2 - m1;

    if (lane == 0) {
        g_idx[t] = i0; g_idx[T_TOK + t] = idx1; g_idx[2 * T_TOK + t] = idx2;
        out_idxf[t] = (float)i0;
        out_idxf[T_TOK + t] = (float)idx1;
        out_idxf[2 * T_TOK + t] = (float)idx2;
        g_flagged[t] = (gap0 < TAU || gap1 < TAU || gap2 < TAU) ? 1 : 0;
        float s = g_ssr[t];
        g_losstok[t] = 3.f * s + 3.f * mv0 + 2.f * mv1 + mv2;
    }
}

// ------------------- compact (R14) -------------------
__global__ __launch_bounds__(256) void k_compact() {
    int i = blockIdx.x * 256 + threadIdx.x;
    for (; i < T_TOK; i += gridDim.x * 256)
        if (g_flagged[i]) g_flaglist[atomicAdd(&g_flagcnt[0], 1)] = i;
}

// ------------------- fixup A v1 (R14-proven): exact zproj -> g_r ---------------------
__global__ __launch_bounds__(256) void k_fixA(const float* __restrict__ z,
                                              const float* __restrict__ Win,
                                              const float* __restrict__ bin) {
    extern __shared__ char sm[];
    float* zsm = (float*)sm;
    float* Wsm = (float*)(sm + 32 * 68 * 4);
    __shared__ int tl[32];
    const int tid = threadIdx.x;
    const int cnt = g_flagcnt[0];
    if (cnt == 0) return;

    for (int base = blockIdx.x * 32; base < cnt; base += gridDim.x * 32) {
        if (tid < 32) tl[tid] = g_flaglist[min(base + tid, cnt - 1)];
        __syncthreads();
        const int tg = tid >> 5, cg = tid & 31;
        float acc[4][8];
#pragma unroll
        for (int a = 0; a < 4; a++)
#pragma unroll
            for (int b = 0; b < 8; b++) acc[a][b] = 0.f;

        for (int kc = 0; kc < D_DIM / 64; kc++) {
#pragma unroll
            for (int q = 0; q < 2; q++) {
                int i = tid + q * 256;
                int s = i >> 4, c4 = i & 15;
                *(float4*)(zsm + s * 68 + c4 * 4) =
                    *(const float4*)(z + (size_t)tl[s] * D_DIM + kc * 64 + c4 * 4);
            }
#pragma unroll
            for (int q = 0; q < 16; q++) {
                int i = tid + q * 256;
                int k = i >> 6, c4 = i & 63;
                *(float4*)(Wsm + k * 256 + c4 * 4) =
                    *(const float4*)(Win + (size_t)(kc * 64 + k) * P_DIM + c4 * 4);
            }
            __syncthreads();
            for (int k = 0; k < 64; k++) {
                float4 w0 = *(const float4*)(Wsm + k * 256 + cg * 8);
                float4 w1 = *(const float4*)(Wsm + k * 256 + cg * 8 + 4);
                float wv[8] = {w0.x, w0.y, w0.z, w0.w, w1.x, w1.y, w1.z, w1.w};
#pragma unroll
                for (int a = 0; a < 4; a++) {
                    float zv = zsm[(tg * 4 + a) * 68 + k];
#pragma unroll
                    for (int b = 0; b < 8; b++)
                        acc[a][b] = __fmaf_rn(zv, wv[b], acc[a][b]);
                }
            }
            __syncthreads();
        }
#pragma unroll
        for (int a = 0; a < 4; a++) {
            int s = tg * 4 + a;
            if (base + s < cnt) {
                float* dst = g_r + (size_t)tl[s] * P_DIM;
#pragma unroll
                for (int b = 0; b < 8; b++)
                    dst[cg * 8 + b] = __fadd_rn(acc[a][b], bin[cg * 8 + b]);
            }
        }
        __syncthreads();
    }
}

// ------------------- fixup B: windowed exact replay (R14-proven) ----------------------
__global__ __launch_bounds__(256) void k_fixB(const float* __restrict__ e0,
                                              const float* __restrict__ e1,
                                              const float* __restrict__ e2,
                                              float* __restrict__ out_idxf) {
    __shared__ float r_sm[8][264];
    __shared__ int cand[8][64];
    __shared__ float ssq_sm[KT];
    const int tid = threadIdx.x, warp = tid >> 5, lane = tid & 31;
    const int cnt = g_flagcnt[0];
    if (cnt == 0) return;
    for (int i = tid; i < KT; i += 256) ssq_sm[i] = g_ssq[i];
    __syncthreads();

    const float* cbl_[3] = {e0, e1, e2};
    const int Kl[3] = {KC0, KC1, KC2};
    const int offl[3] = {0, KC0, KC0 + KC1};

    for (int base = blockIdx.x * 8 + warp; base < cnt; base += gridDim.x * 8) {
        const int t = g_flaglist[base];
#pragma unroll
        for (int k = 0; k < 8; k++)
            r_sm[warp][lane + 32 * k] = g_r[(size_t)t * P_DIM + lane + 32 * k];
        __syncwarp();
        float ssr;
        if (lane == 0) {
            float s = 0.f;
            for (int p = 0; p < P_DIM; p++)
                s = __fadd_rn(s, __fmul_rn(r_sm[warp][p], r_sm[warp][p]));
            ssr = s;
        }
        ssr = __shfl_sync(0xffffffffu, ssr, 0);

        const float* Srow = g_S + (size_t)t * KT;
        int idxs[3];
        double lsd = 0.0;
        int i0 = 0, i1e = 0;
        for (int lvl = 0; lvl < 3; lvl++) {
            const int K = Kl[lvl], off = offl[lvl];
            const float* cb = cbl_[lvl];
            const float* gr0 = (lvl == 1) ? (g_G01 + i0 * KC1)
                             : (lvl == 2) ? (g_G02 + i0 * KC2) : nullptr;
            const float* gr1 = (lvl == 2) ? (g_G12 + i1e * KC2) : nullptr;
            float dd[8];
            float m1 = CUDART_INF_F;
            for (int kc = 0; kc < K / 32; kc++) {
                int j = kc * 32 + lane;
                float sv = Srow[off + j];
                if (gr0) sv -= gr0[j];
                if (gr1) sv -= gr1[j];
                float d = ssq_sm[off + j] - 2.0f * sv;
                dd[kc] = d;
                m1 = fminf(m1, d);
            }
#pragma unroll
            for (int o = 16; o; o >>= 1) m1 = fminf(m1, __shfl_xor_sync(0xffffffffu, m1, o));
            const float thr = m1 + TAU;
            int n = 0;
            for (int kc = 0; kc < K / 32; kc++) {
                unsigned msk = __ballot_sync(0xffffffffu, dd[kc] <= thr);
                if ((dd[kc] <= thr)) {
                    int pos = n + __popc(msk & ((1u << lane) - 1));
                    if (pos < 64) cand[warp][pos] = kc * 32 + lane;
                }
                n += __popc(msk);
            }
            if (n > 64) n = 64;
            __syncwarp();
            float best = CUDART_INF_F; int bi = 0x7fffffff;
            for (int b0 = 0; b0 < n; b0 += 32) {
                int ci = b0 + lane;
                float dex = CUDART_INF_F; int jj = 0x7fffffff;
                if (ci < n) {
                    jj = cand[warp][ci];
                    const float* er = cb + (size_t)jj * P_DIM;
                    float a = 0.f;
                    for (int p = 0; p < P_DIM; p++)
                        a = __fmaf_rn(r_sm[warp][p], er[p], a);
                    dex = __fadd_rn(__fsub_rn(ssr, 2.0f * a), g_ssq[off + jj]);
                }
                float bm = dex; int bj = jj;
#pragma unroll
                for (int o = 16; o; o >>= 1) {
                    float od = __shfl_xor_sync(0xffffffffu, bm, o);
                    int   oi = __shfl_xor_sync(0xffffffffu, bj, o);
                    if (od < bm || (od == bm && oi < bj)) { bm = od; bj = oi; }
                }
                if (bm < best || (bm == best && bj < bi)) { best = bm; bi = bj; }
            }
            idxs[lvl] = bi;
            if (lvl == 0) i0 = bi; else if (lvl == 1) i1e = bi;
            const float* er = cb + (size_t)bi * P_DIM;
            double lp = 0.0;
#pragma unroll
            for (int k = 0; k < 8; k++) {
                int p = lane + 32 * k;
                float nv = __fsub_rn(r_sm[warp][p], er[p]);
                r_sm[warp][p] = nv;
                lp += (double)nv * (double)nv;
            }
            __syncwarp();
#pragma unroll
            for (int o = 16; o; o >>= 1) lp += __shfl_xor_sync(0xffffffffu, lp, o);
            lsd += lp;
            if (lvl < 2) {
                if (lane == 0) {
                    float s = 0.f;
                    for (int p = 0; p < P_DIM; p++)
                        s = __fadd_rn(s, __fmul_rn(r_sm[warp][p], r_sm[warp][p]));
                    ssr = s;
                }
                ssr = __shfl_sync(0xffffffffu, ssr, 0);
            }
        }
        if (lane == 0) {
            g_idx[t] = idxs[0]; g_idx[T_TOK + t] = idxs[1]; g_idx[2 * T_TOK + t] = idxs[2];
            out_idxf[t] = (float)idxs[0];
            out_idxf[T_TOK + t] = (float)idxs[1];
            out_idxf[2 * T_TOK + t] = (float)idxs[2];
            g_losstok[t] = (float)lsd;
        }
        __syncwarp();
    }
}

// ------------------- loss reduce -------------------
__global__ __launch_bounds__(256) void k_lossred(float* __restrict__ out_loss) {
    __shared__ double smm[256];
    double s = 0.0;
    for (int i = threadIdx.x; i < T_TOK; i += 256) s += (double)g_losstok[i];
    smm[threadIdx.x] = s;
    __syncthreads();
    for (int o = 128; o; o >>= 1) {
        if (threadIdx.x < o) smm[threadIdx.x] += smm[threadIdx.x + o];
        __syncthreads();
    }
    if (threadIdx.x == 0)
        *out_loss = (float)(smm[0] * (0.25 / (3.0 * (double)T_TOK * (double)P_DIM)));
}

// ------------------- EW = emb_cat @ W_out -------------------
__global__ __launch_bounds__(256) void k_ew(const float* __restrict__ e0,
                                            const float* __restrict__ e1,
                                            const float* __restrict__ e2,
                                            const float* __restrict__ Wout) {
    __shared__ float a[8][P_DIM];
    const int rbase = blockIdx.x * 8;
    for (int i = threadIdx.x; i < 8 * P_DIM; i += 256) {
        int r = rbase + i / P_DIM, p = i % P_DIM;
        const float* s = (r < KC0) ? (e0 + (size_t)r * P_DIM)
                       : (r < KC0 + KC1) ? (e1 + (size_t)(r - KC0) * P_DIM)
                                         : (e2 + (size_t)(r - KC0 - KC1) * P_DIM);
        a[i / P_DIM][p] = s[p];
    }
    __syncthreads();
    for (int c = threadIdx.x; c < D_DIM; c += 256) {
        float acc[8] = {0.f, 0.f, 0.f, 0.f, 0.f, 0.f, 0.f, 0.f};
        for (int p = 0; p < P_DIM; p++) {
            float w = Wout[(size_t)p * D_DIM + c];
#pragma unroll
            for (int r = 0; r < 8; r++) acc[r] = __fmaf_rn(a[r][p], w, acc[r]);
        }
#pragma unroll
        for (int r = 0; r < 8; r++) g_EW[(size_t)(rbase + r) * D_DIM + c] = acc[r];
    }
}

// ------------------- output gather -------------------
__global__ __launch_bounds__(352) void k_out(const float* __restrict__ bout,
                                             float* __restrict__ out) {
    const int t = blockIdx.x;
    const int i0 = g_idx[t], i1 = g_idx[T_TOK + t], i2 = g_idx[2 * T_TOK + t];
    const float4* r0 = (const float4*)(g_EW + (size_t)i0 * D_DIM);
    const float4* r1 = (const float4*)(g_EW + (size_t)(KC0 + i1) * D_DIM);
    const float4* r2 = (const float4*)(g_EW + (size_t)(KC0 + KC1 + i2) * D_DIM);
    const float4* bb = (const float4*)bout;
    float4* o = (float4*)(out + (size_t)t * D_DIM);
    const int c = threadIdx.x;
    float4 a = r0[c], b = r1[c], cc = r2[c], d = bb[c];
    o[c] = make_float4(a.x + b.x + cc.x + d.x, a.y + b.y + cc.y + d.y,
                       a.z + b.z + cc.z + d.z, a.w + b.w + cc.w + d.w);
}

// ------------------- launch -------------------
extern "C" void kernel_launch(void* const* d_in, const int* in_sizes, int n_in,
                              void* d_out, int out_size) {
    const float* z     = (const float*)d_in[0];
    const float* W_in  = (const float*)d_in[1];
    const float* b_in  = (const float*)d_in[2];
    const float* W_out = (const float*)d_in[3];
    const float* b_out = (const float*)d_in[4];
    const float* e0    = (const float*)d_in[5];
    const float* e1    = (const float*)d_in[6];
    const float* e2    = (const float*)d_in[7];

    float* out      = (float*)d_out;
    float* out_idxf = out + (size_t)T_TOK * D_DIM;
    float* out_loss = out_idxf + 3 * T_TOK;

    cudaFuncSetAttribute(k_fixA, cudaFuncAttributeMaxDynamicSharedMemorySize,
                         32 * 68 * 4 + 64 * 256 * 4);

    k_wprep<<<dim3(D_DIM / 32, P_DIM / 32), 256>>>(W_in);
    k_cbprep<<<KT, 256>>>(e0, e1, e2);
    k_zero1<<<1, 32>>>();
    k_gemm1_mma<<<T_TOK / 128, 512>>>(z, b_in);        // 4th launch -> profiled

    k_ssqE<<<(KT + 7) / 8, 256>>>(e0, e1, e2);
    k_tables<<<7168, 256>>>(e0, e1, e2);
    k_ew<<<KT / 8, 256>>>(e0, e1, e2, W_out);

    k_ssr<<<T_TOK / 8, 256>>>();
    k_gemmS_mma<<<dim3(KT / 64, T_TOK / 128), 256>>>();
    k_pickcas<<<T_TOK / 8, 256>>>(out_idxf);

    k_compact<<<64, 256>>>();
    k_fixA<<<256, 256, 32 * 68 * 4 + 64 * 256 * 4>>>(z, W_in, b_in);
    k_fixB<<<512, 256>>>(e0, e1, e2, out_idxf);

    k_lossred<<<1, 256>>>(out_loss);
    k_out<<<T_TOK, 352>>>(b_out, out);
}